// round 4
// baseline (speedup 1.0000x reference)
#include <cuda_runtime.h>
#include <stdint.h>

// Problem constants
#define NTOK 2048      // B*S = 2*1024
#define HID  1024
#define NEXP 8
#define VOC  32000
#define KVC  2048
#define LSCALE 0.25f   // ALPHA / RANK

// ---------------- scratch (device globals; no allocations) ----------------
__device__ float g_hbuf[NTOK * HID];              // embedded tokens       8 MB
__device__ float g_wmod[NEXP * HID * HID];        // W + la@lb*s          32 MB
__device__ float g_cvec[NEXP * HID];              // cache_vec + expert_b
__device__ float g_partial[2 * NTOK * HID];       // per-slot outputs     16 MB
__device__ int   g_count[NEXP];
__device__ int   g_kcount[NEXP];
__device__ unsigned int g_plist[NEXP * NTOK];     // token | slot<<16
__device__ float g_pw[NEXP * NTOK];
__device__ unsigned char g_self[NEXP * KVC];
__device__ float g_msum[NEXP * HID];

// ---------------- k0: zero routing counters ----------------
__global__ void k_zero() {
    if (threadIdx.x < NEXP) g_count[threadIdx.x] = 0;
}

// ---------------- k1: Wmod[e] = expert_w[e] + scale * la[e] @ lb[e] ----------------
// grid (HID, NEXP), block 256
__global__ void k_wmod(const float* __restrict__ ew, const float* __restrict__ la,
                       const float* __restrict__ lb) {
    int e = blockIdx.y, h = blockIdx.x;
    const float* lar = la + ((size_t)e * HID + h) * 4;
    float a0 = lar[0], a1 = lar[1], a2 = lar[2], a3 = lar[3];
    const float* lbe = lb + (size_t)e * 4 * HID;
    const float* we  = ew + ((size_t)e * HID + h) * HID;
    float* wm = g_wmod + ((size_t)e * HID + h) * HID;
    for (int f = threadIdx.x; f < HID; f += blockDim.x) {
        wm[f] = we[f] + LSCALE * (a0 * lbe[f] + a1 * lbe[HID + f]
                                 + a2 * lbe[2 * HID + f] + a3 * lbe[3 * HID + f]);
    }
}

// ---------------- k2a: exact top-k selection via 32-bit greedy threshold ----------------
// grid NEXP, block 256. importance in [0,1) so uint bit order == float order.
__global__ void k_select(const float* __restrict__ imp) {
    int e = blockIdx.x;
    int n = KVC - 128 * e;
    int k = n / 2;
    __shared__ unsigned int sv[KVC];
    __shared__ int red[256];
    int tid = threadIdx.x;
    for (int i = tid; i < n; i += 256) sv[i] = __float_as_uint(imp[e * KVC + i]);
    __syncthreads();

    unsigned int T = 0;
    for (int bit = 31; bit >= 0; --bit) {
        unsigned int cand = T | (1u << bit);
        int c = 0;
        for (int i = tid; i < n; i += 256) c += (sv[i] >= cand);
        red[tid] = c; __syncthreads();
        for (int s = 128; s > 0; s >>= 1) { if (tid < s) red[tid] += red[tid + s]; __syncthreads(); }
        int cnt = red[0];
        __syncthreads();
        if (cnt >= k) T = cand;
    }
    // strictly-greater count
    int c = 0;
    for (int i = tid; i < n; i += 256) c += (sv[i] > T);
    red[tid] = c; __syncthreads();
    for (int s = 128; s > 0; s >>= 1) { if (tid < s) red[tid] += red[tid + s]; __syncthreads(); }
    int g = red[0];
    __syncthreads();
    for (int i = tid; i < n; i += 256) g_self[e * KVC + i] = (sv[i] > T) ? 1 : 0;
    __syncthreads();
    if (tid == 0) {
        int extra = k - g;  // ties at threshold: lowest indices first (matches lax.top_k)
        for (int i = 0; i < n && extra > 0; i++) {
            if (sv[i] == T) { g_self[e * KVC + i] = 1; extra--; }
        }
        g_kcount[e] = k;
    }
}

// ---------------- k2b: masked column sums of selected cache rows ----------------
// grid (HID/256, NEXP), block 256
__global__ void k_sumsel(const float* __restrict__ cv) {
    int e = blockIdx.y;
    int col = blockIdx.x * 256 + threadIdx.x;
    int n = KVC - 128 * e;
    __shared__ unsigned char fl[KVC];
    for (int i = threadIdx.x; i < n; i += 256) fl[i] = g_self[e * KVC + i];
    __syncthreads();
    float acc = 0.f;
    const float* base = cv + (size_t)e * KVC * HID + col;
    for (int i = 0; i < n; i++)
        if (fl[i]) acc += base[(size_t)i * HID];
    g_msum[e * HID + col] = acc;
}

// ---------------- k2c: cache vec = m + (m@la)@lb*s + expert_b ----------------
// grid NEXP, block 256
__global__ void k_cvec(const float* __restrict__ la, const float* __restrict__ lb,
                       const float* __restrict__ eb) {
    int e = blockIdx.x, tid = threadIdx.x;
    __shared__ float m[HID];
    __shared__ float red[4 * 256];
    float invk = 1.f / (float)g_kcount[e];
    for (int f = tid; f < HID; f += 256) m[f] = g_msum[e * HID + f] * invk;
    __syncthreads();
    float u[4] = {0.f, 0.f, 0.f, 0.f};
    for (int f = tid; f < HID; f += 256) {
        float mv = m[f];
        const float* lr = la + ((size_t)e * HID + f) * 4;
        u[0] += mv * lr[0]; u[1] += mv * lr[1]; u[2] += mv * lr[2]; u[3] += mv * lr[3];
    }
    #pragma unroll
    for (int r = 0; r < 4; r++) red[r * 256 + tid] = u[r];
    __syncthreads();
    for (int s = 128; s > 0; s >>= 1) {
        if (tid < s)
            #pragma unroll
            for (int r = 0; r < 4; r++) red[r * 256 + tid] += red[r * 256 + tid + s];
        __syncthreads();
    }
    float u0 = red[0], u1 = red[256], u2 = red[512], u3 = red[768];
    const float* lbe = lb + (size_t)e * 4 * HID;
    for (int f = tid; f < HID; f += 256) {
        g_cvec[e * HID + f] = m[f]
            + LSCALE * (u0 * lbe[f] + u1 * lbe[HID + f] + u2 * lbe[2 * HID + f] + u3 * lbe[3 * HID + f])
            + eb[e * HID + f];
    }
}

// ---------------- k3: embedding gather + gate + top-2 routing ----------------
// grid NTOK, block 256
__global__ void k_route(const int* __restrict__ x, const float* __restrict__ emb,
                        const float* __restrict__ gw, const float* __restrict__ gb) {
    int t = blockIdx.x, tid = threadIdx.x;
    __shared__ float hs[HID];
    __shared__ float sred[8][8];
    const float* er = emb + (size_t)x[t] * HID;
    float4* hs4 = (float4*)hs;
    float4* hb4 = (float4*)(g_hbuf + (size_t)t * HID);
    for (int i = tid; i < HID / 4; i += 256) {
        float4 v = ((const float4*)er)[i];
        hs4[i] = v; hb4[i] = v;
    }
    __syncthreads();
    float p[8] = {0.f, 0.f, 0.f, 0.f, 0.f, 0.f, 0.f, 0.f};
    for (int i = tid; i < HID; i += 256) {
        float hv = hs[i];
        const float* g = gw + (size_t)i * 8;
        #pragma unroll
        for (int e2 = 0; e2 < 8; e2++) p[e2] += hv * g[e2];
    }
    #pragma unroll
    for (int off = 16; off > 0; off >>= 1)
        #pragma unroll
        for (int e2 = 0; e2 < 8; e2++) p[e2] += __shfl_down_sync(0xffffffffu, p[e2], off);
    int warp = tid / 32, lane = tid % 32;
    if (lane == 0)
        #pragma unroll
        for (int e2 = 0; e2 < 8; e2++) sred[e2][warp] = p[e2];
    __syncthreads();
    if (tid == 0) {
        float lg[8];
        #pragma unroll
        for (int e2 = 0; e2 < 8; e2++) {
            float s = 0.f;
            #pragma unroll
            for (int w = 0; w < 8; w++) s += sred[e2][w];
            lg[e2] = s + gb[e2];
        }
        int i1 = 0;
        #pragma unroll
        for (int e2 = 1; e2 < 8; e2++) if (lg[e2] > lg[i1]) i1 = e2;
        int i2 = -1;
        #pragma unroll
        for (int e2 = 0; e2 < 8; e2++) {
            if (e2 == i1) continue;
            if (i2 < 0 || lg[e2] > lg[i2]) i2 = e2;
        }
        // renormalized top-2 softmax weights: Z cancels
        float w1 = 1.f / (1.f + expf(lg[i2] - lg[i1]));
        float w2 = 1.f - w1;
        int p1 = atomicAdd(&g_count[i1], 1);
        g_plist[i1 * NTOK + p1] = (unsigned)t;
        g_pw[i1 * NTOK + p1] = w1;
        int p2 = atomicAdd(&g_count[i2], 1);
        g_plist[i2 * NTOK + p2] = (unsigned)t | (1u << 16);
        g_pw[i2 * NTOK + p2] = w2;
    }
}

// ---------------- k4: per-expert gathered GEMM, 64x128 tile, BK=16 ----------------
// grid (HID/128, NTOK/64, NEXP), block 256
__global__ void k_egemm() {
    int e = blockIdx.z;
    int cnt = g_count[e];
    int m0 = blockIdx.y * 64;
    if (m0 >= cnt) return;
    int n0 = blockIdx.x * 128;

    __shared__ float As[16][64];
    __shared__ float Bs[16][128];
    __shared__ unsigned int stok[64];
    __shared__ float sw[64];

    int tid = threadIdx.x;
    if (tid < 64) {
        int p = m0 + tid;
        if (p < cnt) { stok[tid] = g_plist[e * NTOK + p]; sw[tid] = g_pw[e * NTOK + p]; }
        else         { stok[tid] = 0u;                    sw[tid] = 0.f; }
    }
    __syncthreads();

    int ty = tid / 16, tx = tid % 16;
    float acc[4][8] = {};
    const float* wm = g_wmod + (size_t)e * HID * HID;

    int am = tid / 4;            // 0..63 token row
    int ak = (tid % 4) * 4;      // k quad
    int bk = tid / 32;           // 0..7
    int bn = (tid % 32) * 4;

    for (int k0 = 0; k0 < HID; k0 += 16) {
        int tok = stok[am] & 0xffff;
        float4 av = *(const float4*)(g_hbuf + (size_t)tok * HID + k0 + ak);
        As[ak + 0][am] = av.x; As[ak + 1][am] = av.y;
        As[ak + 2][am] = av.z; As[ak + 3][am] = av.w;
        #pragma unroll
        for (int r = 0; r < 2; r++) {
            int kk = bk + r * 8;
            float4 bv = *(const float4*)(wm + (size_t)(k0 + kk) * HID + n0 + bn);
            *(float4*)&Bs[kk][bn] = bv;
        }
        __syncthreads();
        #pragma unroll
        for (int kk = 0; kk < 16; kk++) {
            float a[4], b[8];
            #pragma unroll
            for (int i = 0; i < 4; i++) a[i] = As[kk][ty * 4 + i];
            #pragma unroll
            for (int j = 0; j < 8; j++) b[j] = Bs[kk][tx * 8 + j];
            #pragma unroll
            for (int i = 0; i < 4; i++)
                #pragma unroll
                for (int j = 0; j < 8; j++) acc[i][j] = fmaf(a[i], b[j], acc[i][j]);
        }
        __syncthreads();
    }
    #pragma unroll
    for (int i = 0; i < 4; i++) {
        int lm = ty * 4 + i;
        if (m0 + lm >= cnt) continue;
        unsigned int pk = stok[lm];
        int tok = pk & 0xffff, slot = (int)(pk >> 16);
        float w = sw[lm];
        float* outp = g_partial + (size_t)slot * NTOK * HID + (size_t)tok * HID + n0 + tx * 8;
        const float* cp = g_cvec + (size_t)e * HID + n0 + tx * 8;
        #pragma unroll
        for (int j = 0; j < 8; j++) outp[j] = w * (acc[i][j] + cp[j]);
    }
}

// ---------------- k5: vocab GEMM 128x128x16, fuses p0+p1 and bias ----------------
// grid (VOC/128, NTOK/128), block 256
__global__ void k_vgemm(const float* __restrict__ vw, const float* __restrict__ vb,
                        float* __restrict__ out) {
    int n0 = blockIdx.x * 128;
    int m0 = blockIdx.y * 128;
    __shared__ float As[16][128];
    __shared__ float Bs[16][128];
    int tid = threadIdx.x;
    float acc[8][8] = {};
    const float* p0 = g_partial;
    const float* p1 = g_partial + (size_t)NTOK * HID;

    for (int k0 = 0; k0 < HID; k0 += 16) {
        #pragma unroll
        for (int i2 = 0; i2 < 2; i2++) {
            int lin = tid + i2 * 256;           // 0..511 float4 slots
            int m = lin / 4; int kq = (lin % 4) * 4;
            size_t off = (size_t)(m0 + m) * HID + k0 + kq;
            float4 v0 = *(const float4*)(p0 + off);
            float4 v1 = *(const float4*)(p1 + off);
            As[kq + 0][m] = v0.x + v1.x; As[kq + 1][m] = v0.y + v1.y;
            As[kq + 2][m] = v0.z + v1.z; As[kq + 3][m] = v0.w + v1.w;
        }
        #pragma unroll
        for (int i2 = 0; i2 < 2; i2++) {
            int lin = tid + i2 * 256;
            int kk = lin / 32; int nq = (lin % 32) * 4;
            float4 bv = *(const float4*)(vw + (size_t)(k0 + kk) * VOC + n0 + nq);
            *(float4*)&Bs[kk][nq] = bv;
        }
        __syncthreads();
        int ty = tid / 16, tx = tid % 16;
        #pragma unroll
        for (int kk = 0; kk < 16; kk++) {
            float a[8], b[8];
            #pragma unroll
            for (int i = 0; i < 8; i++) a[i] = As[kk][ty * 8 + i];
            #pragma unroll
            for (int j = 0; j < 8; j++) b[j] = Bs[kk][tx * 8 + j];
            #pragma unroll
            for (int i = 0; i < 8; i++)
                #pragma unroll
                for (int j = 0; j < 8; j++) acc[i][j] = fmaf(a[i], b[j], acc[i][j]);
        }
        __syncthreads();
    }
    int ty = tid / 16, tx = tid % 16;
    #pragma unroll
    for (int i = 0; i < 8; i++) {
        int m = m0 + ty * 8 + i;
        float* o = out + (size_t)m * VOC + n0 + tx * 8;
        const float* bb = vb + n0 + tx * 8;
        float4 r0, r1;
        r0.x = acc[i][0] + bb[0]; r0.y = acc[i][1] + bb[1];
        r0.z = acc[i][2] + bb[2]; r0.w = acc[i][3] + bb[3];
        r1.x = acc[i][4] + bb[4]; r1.y = acc[i][5] + bb[5];
        r1.z = acc[i][6] + bb[6]; r1.w = acc[i][7] + bb[7];
        *(float4*)(o + 0) = r0;
        *(float4*)(o + 4) = r1;
    }
}

// ---------------- launch ----------------
extern "C" void kernel_launch(void* const* d_in, const int* in_sizes, int n_in,
                              void* d_out, int out_size) {
    const int*   x    = (const int*)  d_in[0];
    const float* emb  = (const float*)d_in[1];
    const float* gw   = (const float*)d_in[2];
    const float* gb   = (const float*)d_in[3];
    const float* ew   = (const float*)d_in[4];
    const float* eb   = (const float*)d_in[5];
    const float* ela  = (const float*)d_in[6];
    const float* elb  = (const float*)d_in[7];
    const float* cv   = (const float*)d_in[8];
    const float* cimp = (const float*)d_in[9];
    const float* cla  = (const float*)d_in[10];
    const float* clb  = (const float*)d_in[11];
    const float* vw   = (const float*)d_in[12];
    const float* vb   = (const float*)d_in[13];
    float* out = (float*)d_out;

    k_zero<<<1, 32>>>();
    k_wmod<<<dim3(HID, NEXP), 256>>>(ew, ela, elb);
    k_select<<<NEXP, 256>>>(cimp);
    k_sumsel<<<dim3(HID / 256, NEXP), 256>>>(cv);
    k_cvec<<<NEXP, 256>>>(cla, clb, eb);
    k_route<<<NTOK, 256>>>(x, emb, gw, gb);
    k_egemm<<<dim3(HID / 128, NTOK / 64, NEXP), 256>>>();
    k_vgemm<<<dim3(VOC / 128, NTOK / 128), 256>>>(vw, vb, out);
}

// round 9
// speedup vs baseline: 2.1071x; 2.1071x over previous
#include <cuda_runtime.h>
#include <stdint.h>

// Problem constants
#define NTOK 2048      // B*S = 2*1024
#define HID  1024
#define NEXP 8
#define VOC  32000
#define KVC  2048
#define LSCALE 0.25f   // ALPHA / RANK

// ---------------- scratch (device globals; no allocations) ----------------
__device__ float g_hbuf[NTOK * HID];              // embedded tokens       8 MB
__device__ float g_wmod[NEXP * HID * HID];        // W + la@lb*s          32 MB
__device__ float g_cvec[NEXP * HID];              // cache_vec + expert_b
__device__ float g_partial[2 * NTOK * HID];       // per-slot outputs     16 MB
__device__ float g_abuf[NTOK * HID];              // tf32(p0+p1)           8 MB
__device__ float g_wt[(size_t)VOC * HID];         // tf32(vocab_w^T)     125 MB
__device__ int   g_count[NEXP];
__device__ unsigned int g_plist[NEXP * NTOK];     // token | slot<<16
__device__ float g_pw[NEXP * NTOK];
__device__ unsigned char g_self[NEXP * KVC];
__device__ float g_msum_part[NEXP * 8 * HID];

__device__ __forceinline__ float rna_tf32(float x) {
    uint32_t u;
    asm("cvt.rna.tf32.f32 %0, %1;" : "=r"(u) : "f"(x));
    return __uint_as_float(u);
}

// ---------------- k0: zero routing counters ----------------
__global__ void k_zero() {
    if (threadIdx.x < NEXP) g_count[threadIdx.x] = 0;
}

// ---------------- k1: Wmod[e] = expert_w[e] + scale * la[e] @ lb[e] ----------------
__global__ void k_wmod(const float* __restrict__ ew, const float* __restrict__ la,
                       const float* __restrict__ lb) {
    int e = blockIdx.y, h = blockIdx.x;
    const float* lar = la + ((size_t)e * HID + h) * 4;
    float a0 = lar[0], a1 = lar[1], a2 = lar[2], a3 = lar[3];
    const float* lbe = lb + (size_t)e * 4 * HID;
    const float* we  = ew + ((size_t)e * HID + h) * HID;
    float* wm = g_wmod + ((size_t)e * HID + h) * HID;
    for (int f = threadIdx.x; f < HID; f += blockDim.x) {
        wm[f] = we[f] + LSCALE * (a0 * lbe[f] + a1 * lbe[HID + f]
                                 + a2 * lbe[2 * HID + f] + a3 * lbe[3 * HID + f]);
    }
}

// ---------------- k2a: exact top-k selection via 32-bit greedy threshold ----------------
__global__ void k_select(const float* __restrict__ imp) {
    int e = blockIdx.x;
    int n = KVC - 128 * e;
    int k = n / 2;
    __shared__ unsigned int sv[KVC];
    __shared__ int red[256];
    int tid = threadIdx.x;
    for (int i = tid; i < n; i += 256) sv[i] = __float_as_uint(imp[e * KVC + i]);
    __syncthreads();

    unsigned int T = 0;
    for (int bit = 31; bit >= 0; --bit) {
        unsigned int cand = T | (1u << bit);
        int c = 0;
        for (int i = tid; i < n; i += 256) c += (sv[i] >= cand);
        red[tid] = c; __syncthreads();
        for (int s = 128; s > 0; s >>= 1) { if (tid < s) red[tid] += red[tid + s]; __syncthreads(); }
        int cnt = red[0];
        __syncthreads();
        if (cnt >= k) T = cand;
    }
    int c = 0;
    for (int i = tid; i < n; i += 256) c += (sv[i] > T);
    red[tid] = c; __syncthreads();
    for (int s = 128; s > 0; s >>= 1) { if (tid < s) red[tid] += red[tid + s]; __syncthreads(); }
    int g = red[0];
    __syncthreads();
    for (int i = tid; i < n; i += 256) g_self[e * KVC + i] = (sv[i] > T) ? 1 : 0;
    __syncthreads();
    if (tid == 0) {
        int extra = k - g;
        for (int i = 0; i < n && extra > 0; i++) {
            if (sv[i] == T) { g_self[e * KVC + i] = 1; extra--; }
        }
    }
}

// ---------------- k2b: masked column partial sums (deterministic 2-stage) ----------------
// grid (HID/256, NEXP, 8), block 256
__global__ void k_sumsel(const float* __restrict__ cv) {
    int e = blockIdx.y, z = blockIdx.z;
    int col = blockIdx.x * 256 + threadIdx.x;
    int n = KVC - 128 * e;
    int r0 = z * 256;
    int r1 = min(r0 + 256, n);
    __shared__ unsigned char fl[256];
    fl[threadIdx.x] = (r0 + (int)threadIdx.x < r1) ? g_self[e * KVC + r0 + threadIdx.x] : 0;
    __syncthreads();
    float acc = 0.f;
    const float* base = cv + (size_t)e * KVC * HID + (size_t)r0 * HID + col;
    for (int i = 0; i < r1 - r0; i++)
        if (fl[i]) acc += base[(size_t)i * HID];
    g_msum_part[(size_t)(e * 8 + z) * HID + col] = acc;
}

// ---------------- k2c: cache vec = m + (m@la)@lb*s + expert_b ----------------
__global__ void k_cvec(const float* __restrict__ la, const float* __restrict__ lb,
                       const float* __restrict__ eb) {
    int e = blockIdx.x, tid = threadIdx.x;
    __shared__ float m[HID];
    __shared__ float red[4 * 256];
    int k = (KVC - 128 * e) / 2;
    float invk = 1.f / (float)k;
    for (int f = tid; f < HID; f += 256) {
        float s = 0.f;
        #pragma unroll
        for (int z = 0; z < 8; z++) s += g_msum_part[(size_t)(e * 8 + z) * HID + f];
        m[f] = s * invk;
    }
    __syncthreads();
    float u[4] = {0.f, 0.f, 0.f, 0.f};
    for (int f = tid; f < HID; f += 256) {
        float mv = m[f];
        const float* lr = la + ((size_t)e * HID + f) * 4;
        u[0] += mv * lr[0]; u[1] += mv * lr[1]; u[2] += mv * lr[2]; u[3] += mv * lr[3];
    }
    #pragma unroll
    for (int r = 0; r < 4; r++) red[r * 256 + tid] = u[r];
    __syncthreads();
    for (int s = 128; s > 0; s >>= 1) {
        if (tid < s)
            #pragma unroll
            for (int r = 0; r < 4; r++) red[r * 256 + tid] += red[r * 256 + tid + s];
        __syncthreads();
    }
    float u0 = red[0], u1 = red[256], u2 = red[512], u3 = red[768];
    const float* lbe = lb + (size_t)e * 4 * HID;
    for (int f = tid; f < HID; f += 256) {
        g_cvec[e * HID + f] = m[f]
            + LSCALE * (u0 * lbe[f] + u1 * lbe[HID + f] + u2 * lbe[2 * HID + f] + u3 * lbe[3 * HID + f])
            + eb[e * HID + f];
    }
}

// ---------------- k3: embedding gather + gate + top-2 routing ----------------
__global__ void k_route(const int* __restrict__ x, const float* __restrict__ emb,
                        const float* __restrict__ gw, const float* __restrict__ gb) {
    int t = blockIdx.x, tid = threadIdx.x;
    __shared__ float hs[HID];
    __shared__ float sred[8][8];
    const float* er = emb + (size_t)x[t] * HID;
    float4* hs4 = (float4*)hs;
    float4* hb4 = (float4*)(g_hbuf + (size_t)t * HID);
    for (int i = tid; i < HID / 4; i += 256) {
        float4 v = ((const float4*)er)[i];
        hs4[i] = v; hb4[i] = v;
    }
    __syncthreads();
    float p[8] = {0.f, 0.f, 0.f, 0.f, 0.f, 0.f, 0.f, 0.f};
    for (int i = tid; i < HID; i += 256) {
        float hv = hs[i];
        const float* g = gw + (size_t)i * 8;
        #pragma unroll
        for (int e2 = 0; e2 < 8; e2++) p[e2] += hv * g[e2];
    }
    #pragma unroll
    for (int off = 16; off > 0; off >>= 1)
        #pragma unroll
        for (int e2 = 0; e2 < 8; e2++) p[e2] += __shfl_down_sync(0xffffffffu, p[e2], off);
    int warp = tid / 32, lane = tid % 32;
    if (lane == 0)
        #pragma unroll
        for (int e2 = 0; e2 < 8; e2++) sred[e2][warp] = p[e2];
    __syncthreads();
    if (tid == 0) {
        float lg[8];
        #pragma unroll
        for (int e2 = 0; e2 < 8; e2++) {
            float s = 0.f;
            #pragma unroll
            for (int w = 0; w < 8; w++) s += sred[e2][w];
            lg[e2] = s + gb[e2];
        }
        int i1 = 0;
        #pragma unroll
        for (int e2 = 1; e2 < 8; e2++) if (lg[e2] > lg[i1]) i1 = e2;
        int i2 = -1;
        #pragma unroll
        for (int e2 = 0; e2 < 8; e2++) {
            if (e2 == i1) continue;
            if (i2 < 0 || lg[e2] > lg[i2]) i2 = e2;
        }
        float w1 = 1.f / (1.f + expf(lg[i2] - lg[i1]));
        float w2 = 1.f - w1;
        int p1 = atomicAdd(&g_count[i1], 1);
        g_plist[i1 * NTOK + p1] = (unsigned)t;
        g_pw[i1 * NTOK + p1] = w1;
        int p2 = atomicAdd(&g_count[i2], 1);
        g_plist[i2 * NTOK + p2] = (unsigned)t | (1u << 16);
        g_pw[i2 * NTOK + p2] = w2;
    }
}

// ---------------- k4: per-expert gathered GEMM, 64x128 tile, BK=16 (fp32) ----------------
__global__ void k_egemm() {
    int e = blockIdx.z;
    int cnt = g_count[e];
    int m0 = blockIdx.y * 64;
    if (m0 >= cnt) return;
    int n0 = blockIdx.x * 128;

    __shared__ float As[16][64];
    __shared__ float Bs[16][128];
    __shared__ unsigned int stok[64];
    __shared__ float sw[64];

    int tid = threadIdx.x;
    if (tid < 64) {
        int p = m0 + tid;
        if (p < cnt) { stok[tid] = g_plist[e * NTOK + p]; sw[tid] = g_pw[e * NTOK + p]; }
        else         { stok[tid] = 0u;                    sw[tid] = 0.f; }
    }
    __syncthreads();

    int ty = tid / 16, tx = tid % 16;
    float acc[4][8] = {};
    const float* wm = g_wmod + (size_t)e * HID * HID;

    int am = tid / 4;
    int ak = (tid % 4) * 4;
    int bk = tid / 32;
    int bn = (tid % 32) * 4;

    for (int k0 = 0; k0 < HID; k0 += 16) {
        int tok = stok[am] & 0xffff;
        float4 av = *(const float4*)(g_hbuf + (size_t)tok * HID + k0 + ak);
        As[ak + 0][am] = av.x; As[ak + 1][am] = av.y;
        As[ak + 2][am] = av.z; As[ak + 3][am] = av.w;
        #pragma unroll
        for (int r = 0; r < 2; r++) {
            int kk = bk + r * 8;
            float4 bv = *(const float4*)(wm + (size_t)(k0 + kk) * HID + n0 + bn);
            *(float4*)&Bs[kk][bn] = bv;
        }
        __syncthreads();
        #pragma unroll
        for (int kk = 0; kk < 16; kk++) {
            float a[4], b[8];
            #pragma unroll
            for (int i = 0; i < 4; i++) a[i] = As[kk][ty * 4 + i];
            #pragma unroll
            for (int j = 0; j < 8; j++) b[j] = Bs[kk][tx * 8 + j];
            #pragma unroll
            for (int i = 0; i < 4; i++)
                #pragma unroll
                for (int j = 0; j < 8; j++) acc[i][j] = fmaf(a[i], b[j], acc[i][j]);
        }
        __syncthreads();
    }
    #pragma unroll
    for (int i = 0; i < 4; i++) {
        int lm = ty * 4 + i;
        if (m0 + lm >= cnt) continue;
        unsigned int pk = stok[lm];
        int tok = pk & 0xffff, slot = (int)(pk >> 16);
        float w = sw[lm];
        float* outp = g_partial + (size_t)slot * NTOK * HID + (size_t)tok * HID + n0 + tx * 8;
        const float* cp = g_cvec + (size_t)e * HID + n0 + tx * 8;
        #pragma unroll
        for (int j = 0; j < 8; j++) outp[j] = w * (acc[i][j] + cp[j]);
    }
}

// ---------------- k_aprep: A = rna_tf32(p0 + p1) ----------------
__global__ void k_aprep() {
    int m = blockIdx.x;
    const float4* p0 = (const float4*)(g_partial + (size_t)m * HID);
    const float4* p1 = (const float4*)(g_partial + (size_t)NTOK * HID + (size_t)m * HID);
    float4* a = (float4*)(g_abuf + (size_t)m * HID);
    int i = threadIdx.x;
    float4 v0 = p0[i], v1 = p1[i];
    float4 r;
    r.x = rna_tf32(v0.x + v1.x); r.y = rna_tf32(v0.y + v1.y);
    r.z = rna_tf32(v0.z + v1.z); r.w = rna_tf32(v0.w + v1.w);
    a[i] = r;
}

// ---------------- k_wt: g_wt[n][k] = rna_tf32(vocab_w[k][n]) ----------------
// grid (VOC/64, HID/64), block 256
__global__ void k_wt(const float* __restrict__ vw) {
    __shared__ float ts[64][65];
    int n0 = blockIdx.x * 64, k0 = blockIdx.y * 64;
    int tid = threadIdx.x;
    #pragma unroll
    for (int r = 0; r < 16; r++) {
        int idx = tid + r * 256;
        int kk = idx / 64, nn = idx % 64;
        ts[kk][nn] = vw[(size_t)(k0 + kk) * VOC + n0 + nn];
    }
    __syncthreads();
    #pragma unroll
    for (int r = 0; r < 16; r++) {
        int idx = tid + r * 256;
        int nn = idx / 64, kk = idx % 64;
        g_wt[(size_t)(n0 + nn) * HID + k0 + kk] = rna_tf32(ts[kk][nn]);
    }
}

// ---------------- k_vgemm_mma: tf32 mma.sync GEMM, 128x128x16 tiles ----------------
// grid (NTOK/128=16, VOC/128=250), block 256 (8 warps = 2m x 4n, warp tile 64x32)
// Smem fragment layouts (double buffered, conflict-free by construction):
//   Af[s][mt][r][lane]  (2*8*4*32 floats)  a-reg r of m16n8k8 frag
//   Bf[s][nt][r][lane]  (2*16*2*32 floats) b-reg r
// Stores use an element skew c=(j+kq/4)&3 so warp STS hits 32 distinct banks.
__global__ void __launch_bounds__(256, 2) k_vgemm_mma(const float* __restrict__ vb,
                                                      float* __restrict__ out) {
    __shared__ float Af[2][2048];
    __shared__ float Bf[2][2048];
    int tid = threadIdx.x;
    int lane = tid & 31, wid = tid >> 5;
    int wm = wid >> 2, wn = wid & 3;                 // 2 x 4 warps
    int m0 = blockIdx.x * 128, n0 = blockIdx.y * 128;
    const float* Ag = g_abuf + (size_t)m0 * HID;
    const float* Bg = g_wt   + (size_t)n0 * HID;

    float acc[16][4];
    #pragma unroll
    for (int i = 0; i < 16; i++) {
        acc[i][0] = 0.f; acc[i][1] = 0.f; acc[i][2] = 0.f; acc[i][3] = 0.f;
    }

    int row0 = tid >> 2;               // it adds +64
    int kq   = (tid & 3) << 2;         // 0,4,8,12
    int q    = kq >> 2;                // skew seed
    int s_   = kq >> 3;                // k-step 0/1
    int kh   = (kq >> 2) & 1;          // k-half within step
    int rB   = kh;                     // b-frag reg

    float4 aR[2], bR[2];

#define LOADG(K0)                                                              \
    _Pragma("unroll") for (int it = 0; it < 2; it++) {                         \
        int row = row0 + it * 64;                                              \
        aR[it] = *(const float4*)(Ag + (size_t)row * HID + (K0) + kq);         \
        bR[it] = *(const float4*)(Bg + (size_t)row * HID + (K0) + kq);         \
    }

#define STAGE(BUF)                                                             \
    _Pragma("unroll") for (int it = 0; it < 2; it++) {                         \
        int row = row0 + it * 64;                                              \
        int mt = row >> 4, lr = row & 15;                                      \
        int nt = row >> 3, nr = row & 7;                                       \
        int ra = (lr >> 3) + 2 * kh;                                           \
        float va[4], vbv[4];                                                   \
        *(float4*)va = aR[it]; *(float4*)vbv = bR[it];                         \
        _Pragma("unroll") for (int j = 0; j < 4; j++) {                        \
            int c = (j + q) & 3;                                               \
            Af[BUF][((((s_ * 8 + mt) << 2) + ra) << 5) + ((lr & 7) << 2) + c] = va[c];  \
            Bf[BUF][((((s_ * 16 + nt) << 1) + rB) << 5) + (nr << 2) + c]      = vbv[c]; \
        }                                                                      \
    }

#define COMPUTE(BUF)                                                           \
    _Pragma("unroll") for (int ss = 0; ss < 2; ss++) {                         \
        uint32_t bfr[4][2];                                                    \
        _Pragma("unroll") for (int nt = 0; nt < 4; nt++)                       \
            _Pragma("unroll") for (int r = 0; r < 2; r++)                      \
                bfr[nt][r] = __float_as_uint(                                  \
                    Bf[BUF][((((ss * 16 + wn * 4 + nt) << 1) + r) << 5) + lane]); \
        _Pragma("unroll") for (int mt = 0; mt < 4; mt++) {                     \
            uint32_t afr[4];                                                   \
            _Pragma("unroll") for (int r = 0; r < 4; r++)                      \
                afr[r] = __float_as_uint(                                      \
                    Af[BUF][((((ss * 8 + wm * 4 + mt) << 2) + r) << 5) + lane]); \
            _Pragma("unroll") for (int nt = 0; nt < 4; nt++) {                 \
                float* d = acc[mt * 4 + nt];                                   \
                asm volatile(                                                  \
                    "mma.sync.aligned.m16n8k8.row.col.f32.tf32.tf32.f32 "      \
                    "{%0,%1,%2,%3}, {%4,%5,%6,%7}, {%8,%9}, {%0,%1,%2,%3};"    \
                    : "+f"(d[0]), "+f"(d[1]), "+f"(d[2]), "+f"(d[3])           \
                    : "r"(afr[0]), "r"(afr[1]), "r"(afr[2]), "r"(afr[3]),      \
                      "r"(bfr[nt][0]), "r"(bfr[nt][1]));                       \
            }                                                                  \
        }                                                                      \
    }

    LOADG(0);
    STAGE(0);
    __syncthreads();
    int buf = 0;
    for (int kt = 1; kt <= HID / 16; kt++) {
        if (kt < HID / 16) LOADG(kt * 16);
        COMPUTE(buf);
        if (kt < HID / 16) {
            STAGE(buf ^ 1);
            __syncthreads();
            buf ^= 1;
        }
    }

    // epilogue: c0=(r,2c) c1=(r,2c+1) c2=(r+8,2c) c3=(r+8,2c+1)
    int rr = lane >> 2, cc = (lane & 3) * 2;
    #pragma unroll
    for (int mt = 0; mt < 4; mt++) {
        int m = m0 + wm * 64 + mt * 16 + rr;
        #pragma unroll
        for (int nt = 0; nt < 4; nt++) {
            int n = n0 + wn * 32 + nt * 8 + cc;
            const float* d = acc[mt * 4 + nt];
            float2 bb = *(const float2*)(vb + n);
            float2 o0 = make_float2(d[0] + bb.x, d[1] + bb.y);
            float2 o1 = make_float2(d[2] + bb.x, d[3] + bb.y);
            *(float2*)(out + (size_t)m * VOC + n) = o0;
            *(float2*)(out + (size_t)(m + 8) * VOC + n) = o1;
        }
    }
#undef LOADG
#undef STAGE
#undef COMPUTE
}

// ---------------- launch ----------------
extern "C" void kernel_launch(void* const* d_in, const int* in_sizes, int n_in,
                              void* d_out, int out_size) {
    const int*   x    = (const int*)  d_in[0];
    const float* emb  = (const float*)d_in[1];
    const float* gw   = (const float*)d_in[2];
    const float* gb   = (const float*)d_in[3];
    const float* ew   = (const float*)d_in[4];
    const float* eb   = (const float*)d_in[5];
    const float* ela  = (const float*)d_in[6];
    const float* elb  = (const float*)d_in[7];
    const float* cv   = (const float*)d_in[8];
    const float* cimp = (const float*)d_in[9];
    const float* cla  = (const float*)d_in[10];
    const float* clb  = (const float*)d_in[11];
    const float* vw   = (const float*)d_in[12];
    const float* vb   = (const float*)d_in[13];
    float* out = (float*)d_out;

    k_zero<<<1, 32>>>();
    k_wmod<<<dim3(HID, NEXP), 256>>>(ew, ela, elb);
    k_select<<<NEXP, 256>>>(cimp);
    k_sumsel<<<dim3(HID / 256, NEXP, 8), 256>>>(cv);
    k_cvec<<<NEXP, 256>>>(cla, clb, eb);
    k_route<<<NTOK, 256>>>(x, emb, gw, gb);
    k_egemm<<<dim3(HID / 128, NTOK / 64, NEXP), 256>>>();
    k_aprep<<<NTOK, 256>>>();
    k_wt<<<dim3(VOC / 64, HID / 64), 256>>>(vw);
    k_vgemm_mma<<<dim3(NTOK / 128, VOC / 128), 256>>>(vb, out);
}

// round 12
// speedup vs baseline: 4.1174x; 1.9540x over previous
#include <cuda_runtime.h>
#include <stdint.h>

// Problem constants
#define NTOK 2048      // B*S = 2*1024
#define HID  1024
#define NEXP 8
#define VOC  32000
#define KVC  2048
#define LSCALE 0.25f   // ALPHA / RANK

// ---------------- scratch (device globals; no allocations) ----------------
__device__ float g_hbuf[NTOK * HID];              // tf32 embedded tokens  8 MB
__device__ float g_wmod[NEXP * HID * HID];        // tf32 (W+la@lb*s)^T   32 MB  [e][f][h]
__device__ float g_cvec[NEXP * HID];              // cache_vec + expert_b
__device__ float g_partial[2 * NTOK * HID];       // per-slot outputs     16 MB
__device__ float g_abuf[NTOK * HID];              // tf32(p0+p1)           8 MB
__device__ float g_wt[(size_t)VOC * HID];         // tf32(vocab_w^T)     125 MB  [n][k]
__device__ int   g_count[NEXP];
__device__ unsigned int g_plist[NEXP * NTOK];     // token | slot<<16
__device__ float g_pw[NEXP * NTOK];
__device__ unsigned char g_self[NEXP * KVC];
__device__ float g_msum_part[NEXP * 8 * HID];

__device__ __forceinline__ float rna_tf32(float x) {
    uint32_t u;
    asm("cvt.rna.tf32.f32 %0, %1;" : "=r"(u) : "f"(x));
    return __uint_as_float(u);
}
__device__ __forceinline__ uint32_t smem_u32(const void* p) {
    uint32_t a;
    asm("{ .reg .u64 t; cvta.to.shared.u64 t, %1; cvt.u32.u64 %0, t; }" : "=r"(a) : "l"(p));
    return a;
}
__device__ __forceinline__ void cp16(uint32_t dst, const void* src) {
    asm volatile("cp.async.cg.shared.global [%0], [%1], 16;" :: "r"(dst), "l"(src) : "memory");
}
#define CP_COMMIT() asm volatile("cp.async.commit_group;" ::: "memory")
#define CP_WAIT1()  asm volatile("cp.async.wait_group 1;" ::: "memory")
#define CP_WAIT0()  asm volatile("cp.async.wait_group 0;" ::: "memory")

#define LDMX4(a0,a1,a2,a3,addr) \
    asm volatile("ldmatrix.sync.aligned.m8n8.x4.shared.b16 {%0,%1,%2,%3}, [%4];" \
        : "=r"(a0), "=r"(a1), "=r"(a2), "=r"(a3) : "r"(addr))
#define LDMX2(b0,b1,addr) \
    asm volatile("ldmatrix.sync.aligned.m8n8.x2.shared.b16 {%0,%1}, [%2];" \
        : "=r"(b0), "=r"(b1) : "r"(addr))
#define MMA_TF32(d, A0,A1,A2,A3, B0,B1) \
    asm volatile("mma.sync.aligned.m16n8k8.row.col.f32.tf32.tf32.f32 " \
        "{%0,%1,%2,%3}, {%4,%5,%6,%7}, {%8,%9}, {%0,%1,%2,%3};" \
        : "+f"((d)[0]), "+f"((d)[1]), "+f"((d)[2]), "+f"((d)[3]) \
        : "r"(A0), "r"(A1), "r"(A2), "r"(A3), "r"(B0), "r"(B1))

// ---------------- k0: zero routing counters ----------------
__global__ void k_zero() {
    if (threadIdx.x < NEXP) g_count[threadIdx.x] = 0;
}

// ---------------- k_wmodT: g_wmod[e][f][h] = tf32(ew[e][h][f] + s*la@lb) ----------------
// grid (HID/64 f-tiles, HID/64 h-tiles, NEXP), block 256
__global__ void k_wmodT(const float* __restrict__ ew, const float* __restrict__ la,
                        const float* __restrict__ lb) {
    __shared__ float ts[64][65];
    int e = blockIdx.z;
    int n0 = blockIdx.x * 64, k0 = blockIdx.y * 64;
    int tid = threadIdx.x;
    const float* lbe = lb + (size_t)e * 4 * HID;
    #pragma unroll
    for (int r = 0; r < 16; r++) {
        int idx = tid + r * 256;
        int kk = idx / 64, nn = idx % 64;
        int h = k0 + kk, f = n0 + nn;
        const float* lar = la + ((size_t)e * HID + h) * 4;
        float v = ew[((size_t)e * HID + h) * HID + f]
                + LSCALE * (lar[0] * lbe[f] + lar[1] * lbe[HID + f]
                           + lar[2] * lbe[2 * HID + f] + lar[3] * lbe[3 * HID + f]);
        ts[kk][nn] = v;
    }
    __syncthreads();
    #pragma unroll
    for (int r = 0; r < 16; r++) {
        int idx = tid + r * 256;
        int nn = idx / 64, kk = idx % 64;
        g_wmod[((size_t)e * HID + (n0 + nn)) * HID + k0 + kk] = rna_tf32(ts[kk][nn]);
    }
}

// ---------------- k2a: exact top-k selection via 32-bit greedy threshold ----------------
__global__ void k_select(const float* __restrict__ imp) {
    int e = blockIdx.x;
    int n = KVC - 128 * e;
    int k = n / 2;
    __shared__ unsigned int sv[KVC];
    __shared__ int red[256];
    int tid = threadIdx.x;
    for (int i = tid; i < n; i += 256) sv[i] = __float_as_uint(imp[e * KVC + i]);
    __syncthreads();

    unsigned int T = 0;
    for (int bit = 31; bit >= 0; --bit) {
        unsigned int cand = T | (1u << bit);
        int c = 0;
        for (int i = tid; i < n; i += 256) c += (sv[i] >= cand);
        red[tid] = c; __syncthreads();
        for (int s = 128; s > 0; s >>= 1) { if (tid < s) red[tid] += red[tid + s]; __syncthreads(); }
        int cnt = red[0];
        __syncthreads();
        if (cnt >= k) T = cand;
    }
    int c = 0;
    for (int i = tid; i < n; i += 256) c += (sv[i] > T);
    red[tid] = c; __syncthreads();
    for (int s = 128; s > 0; s >>= 1) { if (tid < s) red[tid] += red[tid + s]; __syncthreads(); }
    int g = red[0];
    __syncthreads();
    for (int i = tid; i < n; i += 256) g_self[e * KVC + i] = (sv[i] > T) ? 1 : 0;
    __syncthreads();
    if (tid == 0) {
        int extra = k - g;
        for (int i = 0; i < n && extra > 0; i++) {
            if (sv[i] == T) { g_self[e * KVC + i] = 1; extra--; }
        }
    }
}

// ---------------- k2b: masked column partial sums (deterministic 2-stage) ----------------
__global__ void k_sumsel(const float* __restrict__ cv) {
    int e = blockIdx.y, z = blockIdx.z;
    int col = blockIdx.x * 256 + threadIdx.x;
    int n = KVC - 128 * e;
    int r0 = z * 256;
    int r1 = min(r0 + 256, n);
    __shared__ unsigned char fl[256];
    fl[threadIdx.x] = (r0 + (int)threadIdx.x < r1) ? g_self[e * KVC + r0 + threadIdx.x] : 0;
    __syncthreads();
    float acc = 0.f;
    const float* base = cv + (size_t)e * KVC * HID + (size_t)r0 * HID + col;
    for (int i = 0; i < r1 - r0; i++)
        if (fl[i]) acc += base[(size_t)i * HID];
    g_msum_part[(size_t)(e * 8 + z) * HID + col] = acc;
}

// ---------------- k2c: cache vec = m + (m@la)@lb*s + expert_b ----------------
__global__ void k_cvec(const float* __restrict__ la, const float* __restrict__ lb,
                       const float* __restrict__ eb) {
    int e = blockIdx.x, tid = threadIdx.x;
    __shared__ float m[HID];
    __shared__ float red[4 * 256];
    int k = (KVC - 128 * e) / 2;
    float invk = 1.f / (float)k;
    for (int f = tid; f < HID; f += 256) {
        float s = 0.f;
        #pragma unroll
        for (int z = 0; z < 8; z++) s += g_msum_part[(size_t)(e * 8 + z) * HID + f];
        m[f] = s * invk;
    }
    __syncthreads();
    float u[4] = {0.f, 0.f, 0.f, 0.f};
    for (int f = tid; f < HID; f += 256) {
        float mv = m[f];
        const float* lr = la + ((size_t)e * HID + f) * 4;
        u[0] += mv * lr[0]; u[1] += mv * lr[1]; u[2] += mv * lr[2]; u[3] += mv * lr[3];
    }
    #pragma unroll
    for (int r = 0; r < 4; r++) red[r * 256 + tid] = u[r];
    __syncthreads();
    for (int s = 128; s > 0; s >>= 1) {
        if (tid < s)
            #pragma unroll
            for (int r = 0; r < 4; r++) red[r * 256 + tid] += red[r * 256 + tid + s];
        __syncthreads();
    }
    float u0 = red[0], u1 = red[256], u2 = red[512], u3 = red[768];
    const float* lbe = lb + (size_t)e * 4 * HID;
    for (int f = tid; f < HID; f += 256) {
        g_cvec[e * HID + f] = m[f]
            + LSCALE * (u0 * lbe[f] + u1 * lbe[HID + f] + u2 * lbe[2 * HID + f] + u3 * lbe[3 * HID + f])
            + eb[e * HID + f];
    }
}

// ---------------- k3: embedding gather + gate + top-2 routing ----------------
// g_hbuf rows are stored rna-tf32 (consumed only by the tf32 expert GEMM)
__global__ void k_route(const int* __restrict__ x, const float* __restrict__ emb,
                        const float* __restrict__ gw, const float* __restrict__ gb) {
    int t = blockIdx.x, tid = threadIdx.x;
    __shared__ float hs[HID];
    __shared__ float sred[8][8];
    const float* er = emb + (size_t)x[t] * HID;
    float4* hs4 = (float4*)hs;
    float4* hb4 = (float4*)(g_hbuf + (size_t)t * HID);
    for (int i = tid; i < HID / 4; i += 256) {
        float4 v = ((const float4*)er)[i];
        hs4[i] = v;
        float4 w;
        w.x = rna_tf32(v.x); w.y = rna_tf32(v.y);
        w.z = rna_tf32(v.z); w.w = rna_tf32(v.w);
        hb4[i] = w;
    }
    __syncthreads();
    float p[8] = {0.f, 0.f, 0.f, 0.f, 0.f, 0.f, 0.f, 0.f};
    for (int i = tid; i < HID; i += 256) {
        float hv = hs[i];
        const float* g = gw + (size_t)i * 8;
        #pragma unroll
        for (int e2 = 0; e2 < 8; e2++) p[e2] += hv * g[e2];
    }
    #pragma unroll
    for (int off = 16; off > 0; off >>= 1)
        #pragma unroll
        for (int e2 = 0; e2 < 8; e2++) p[e2] += __shfl_down_sync(0xffffffffu, p[e2], off);
    int warp = tid / 32, lane = tid % 32;
    if (lane == 0)
        #pragma unroll
        for (int e2 = 0; e2 < 8; e2++) sred[e2][warp] = p[e2];
    __syncthreads();
    if (tid == 0) {
        float lg[8];
        #pragma unroll
        for (int e2 = 0; e2 < 8; e2++) {
            float s = 0.f;
            #pragma unroll
            for (int w = 0; w < 8; w++) s += sred[e2][w];
            lg[e2] = s + gb[e2];
        }
        int i1 = 0;
        #pragma unroll
        for (int e2 = 1; e2 < 8; e2++) if (lg[e2] > lg[i1]) i1 = e2;
        int i2 = -1;
        #pragma unroll
        for (int e2 = 0; e2 < 8; e2++) {
            if (e2 == i1) continue;
            if (i2 < 0 || lg[e2] > lg[i2]) i2 = e2;
        }
        float w1 = 1.f / (1.f + expf(lg[i2] - lg[i1]));
        float w2 = 1.f - w1;
        int p1 = atomicAdd(&g_count[i1], 1);
        g_plist[i1 * NTOK + p1] = (unsigned)t;
        g_pw[i1 * NTOK + p1] = w1;
        int p2 = atomicAdd(&g_count[i2], 1);
        g_plist[i2 * NTOK + p2] = (unsigned)t | (1u << 16);
        g_pw[i2 * NTOK + p2] = w2;
    }
}

// ---------------- k_egemm2: per-expert gathered tf32 mma GEMM, 64x128 tile ----------------
// grid (HID/128, NTOK/64, NEXP), block 256 (8 warps = 2m x 4n, warp tile 32x32)
// smem (dynamic, 48KB): A[2][64][32] swz + B[2][128][32] swz; cp.async 2-stage
__global__ void __launch_bounds__(256, 2) k_egemm2() {
    extern __shared__ float esm[];
    __shared__ unsigned int stok[64];
    __shared__ float swt[64];

    int e = blockIdx.z;
    int cnt = g_count[e];
    int m0 = blockIdx.y * 64;
    if (m0 >= cnt) return;
    int n0 = blockIdx.x * 128;

    int tid = threadIdx.x;
    int lane = tid & 31, wid = tid >> 5;
    int wm = wid >> 2, wn = wid & 3;
    uint32_t sbase = smem_u32(esm);

    if (tid < 64) {
        int p = m0 + tid;
        if (p < cnt) { stok[tid] = g_plist[e * NTOK + p]; swt[tid] = g_pw[e * NTOK + p]; }
        else         { stok[tid] = 0u;                    swt[tid] = 0.f; }
    }
    __syncthreads();

    const float* wmT = g_wmod + (size_t)e * HID * HID;

    // cp.async row/slot assignment
    int aRow = tid >> 3;             // used with +32 for second A op? A: 512 f4 = idx 0..511
    (void)aRow;

#define EG_ISSUE(STAGE, BUF) do {                                              \
    int k0 = (STAGE) * 32;                                                     \
    _Pragma("unroll") for (int j = 0; j < 2; j++) {                            \
        int idx = tid + j * 256;                                               \
        int row = idx >> 3, slot = idx & 7;                                    \
        int tok = (int)(stok[row] & 0xffffu);                                  \
        uint32_t dst = sbase + (uint32_t)(BUF) * 8192u                         \
                     + (uint32_t)(row * 128 + ((slot ^ (row & 7)) << 4));      \
        cp16(dst, g_hbuf + (size_t)tok * HID + k0 + slot * 4);                 \
    }                                                                          \
    _Pragma("unroll") for (int j = 0; j < 4; j++) {                            \
        int idx = tid + j * 256;                                               \
        int row = idx >> 3, slot = idx & 7;                                    \
        uint32_t dst = sbase + 16384u + (uint32_t)(BUF) * 16384u               \
                     + (uint32_t)(row * 128 + ((slot ^ (row & 7)) << 4));      \
        cp16(dst, wmT + (size_t)(n0 + row) * HID + k0 + slot * 4);             \
    }                                                                          \
    CP_COMMIT();                                                               \
} while (0)

    float acc[8][4];
    #pragma unroll
    for (int i = 0; i < 8; i++) { acc[i][0]=0.f; acc[i][1]=0.f; acc[i][2]=0.f; acc[i][3]=0.f; }

    // ldmatrix per-lane constants
    int tileA = lane >> 3;
    int rlA   = ((tileA & 1) << 3) + (lane & 7);
    int thiA  = tileA >> 1;
    int r7A   = lane & 7;
    uint32_t aRowByte = (uint32_t)((wm * 32 + rlA) * 128);
    int l16 = lane & 15;
    int tB  = l16 >> 3;
    int rlB = l16 & 7;
    uint32_t bRowByte = (uint32_t)((wn * 32 + rlB) * 128);

    EG_ISSUE(0, 0);
    int buf = 0;
    const int NST = HID / 32;
    for (int s = 0; s < NST; s++) {
        if (s + 1 < NST) { EG_ISSUE(s + 1, buf ^ 1); CP_WAIT1(); }
        else             { CP_WAIT0(); }
        __syncthreads();
        uint32_t Ab = sbase + (uint32_t)buf * 8192u;
        uint32_t Bb = sbase + 16384u + (uint32_t)buf * 16384u;
        #pragma unroll
        for (int ss = 0; ss < 4; ss++) {
            uint32_t b0[4], b1[4];
            #pragma unroll
            for (int nt = 0; nt < 4; nt++) {
                uint32_t addr = Bb + bRowByte + (uint32_t)(nt * 1024)
                              + (uint32_t)(((ss * 2 + tB) ^ rlB) << 4);
                LDMX2(b0[nt], b1[nt], addr);
            }
            #pragma unroll
            for (int mt = 0; mt < 2; mt++) {
                uint32_t a0, a1, a2, a3;
                uint32_t addr = Ab + aRowByte + (uint32_t)(mt * 2048)
                              + (uint32_t)(((ss * 2 + thiA) ^ r7A) << 4);
                LDMX4(a0, a1, a2, a3, addr);
                #pragma unroll
                for (int nt = 0; nt < 4; nt++)
                    MMA_TF32(acc[mt * 4 + nt], a0, a1, a2, a3, b0[nt], b1[nt]);
            }
        }
        __syncthreads();
        buf ^= 1;
    }

    // epilogue: out[slot][tok][n] = w * (acc + cvec)
    int rr = lane >> 2, cc = (lane & 3) * 2;
    #pragma unroll
    for (int mt = 0; mt < 2; mt++) {
        #pragma unroll
        for (int half = 0; half < 2; half++) {
            int ml = wm * 32 + mt * 16 + rr + half * 8;
            if (m0 + ml >= cnt) continue;
            unsigned int pk = stok[ml];
            int tok = (int)(pk & 0xffffu), slot = (int)(pk >> 16);
            float w = swt[ml];
            float* outp = g_partial + (size_t)slot * NTOK * HID + (size_t)tok * HID;
            #pragma unroll
            for (int nt = 0; nt < 4; nt++) {
                int n = n0 + wn * 32 + nt * 8 + cc;
                const float* d = acc[mt * 4 + nt];
                float cv0 = g_cvec[e * HID + n], cv1 = g_cvec[e * HID + n + 1];
                float2 o;
                o.x = w * (d[half * 2 + 0] + cv0);
                o.y = w * (d[half * 2 + 1] + cv1);
                *(float2*)(outp + n) = o;
            }
        }
    }
#undef EG_ISSUE
}

// ---------------- k_aprep: A = rna_tf32(p0 + p1) ----------------
__global__ void k_aprep() {
    int m = blockIdx.x;
    const float4* p0 = (const float4*)(g_partial + (size_t)m * HID);
    const float4* p1 = (const float4*)(g_partial + (size_t)NTOK * HID + (size_t)m * HID);
    float4* a = (float4*)(g_abuf + (size_t)m * HID);
    int i = threadIdx.x;
    float4 v0 = p0[i], v1 = p1[i];
    float4 r;
    r.x = rna_tf32(v0.x + v1.x); r.y = rna_tf32(v0.y + v1.y);
    r.z = rna_tf32(v0.z + v1.z); r.w = rna_tf32(v0.w + v1.w);
    a[i] = r;
}

// ---------------- k_wt: g_wt[n][k] = rna_tf32(vocab_w[k][n]) ----------------
// grid (VOC/64, HID/64), block 256
__global__ void k_wt(const float* __restrict__ vw) {
    __shared__ float ts[64][65];
    int n0 = blockIdx.x * 64, k0 = blockIdx.y * 64;
    int tid = threadIdx.x;
    #pragma unroll
    for (int r = 0; r < 16; r++) {
        int idx = tid + r * 256;
        int kk = idx / 64, nn = idx % 64;
        ts[kk][nn] = vw[(size_t)(k0 + kk) * VOC + n0 + nn];
    }
    __syncthreads();
    #pragma unroll
    for (int r = 0; r < 16; r++) {
        int idx = tid + r * 256;
        int nn = idx / 64, kk = idx % 64;
        g_wt[(size_t)(n0 + nn) * HID + k0 + kk] = rna_tf32(ts[kk][nn]);
    }
}

// ---------------- k_vgemm2: tf32 mma GEMM, 128x128 tile, cp.async + ldmatrix ----------------
// grid (NTOK/128=16, VOC/128=250), block 256 (8 warps = 2m x 4n, warp tile 64x32)
// smem (dynamic, 64KB): A[2][128][32] swz + B[2][128][32] swz; 2-stage cp.async
__global__ void __launch_bounds__(256, 2) k_vgemm2(const float* __restrict__ vb,
                                                   float* __restrict__ out) {
    extern __shared__ float vsm[];
    int tid = threadIdx.x;
    int lane = tid & 31, wid = tid >> 5;
    int wm = wid >> 2, wn = wid & 3;
    int m0 = blockIdx.x * 128, n0 = blockIdx.y * 128;
    const float* Ag = g_abuf + (size_t)m0 * HID;
    const float* Bg = g_wt   + (size_t)n0 * HID;
    uint32_t sbase = smem_u32(vsm);

#define VG_ISSUE(STAGE, BUF) do {                                              \
    int k0 = (STAGE) * 32;                                                     \
    _Pragma("unroll") for (int j = 0; j < 4; j++) {                            \
        int idx = tid + j * 256;                                               \
        int row = idx >> 3, slot = idx & 7;                                    \
        uint32_t so = (uint32_t)(row * 128 + ((slot ^ (row & 7)) << 4));       \
        cp16(sbase + (uint32_t)(BUF) * 16384u + so,                            \
             Ag + (size_t)row * HID + k0 + slot * 4);                          \
        cp16(sbase + 32768u + (uint32_t)(BUF) * 16384u + so,                   \
             Bg + (size_t)row * HID + k0 + slot * 4);                          \
    }                                                                          \
    CP_COMMIT();                                                               \
} while (0)

    float acc[16][4];
    #pragma unroll
    for (int i = 0; i < 16; i++) { acc[i][0]=0.f; acc[i][1]=0.f; acc[i][2]=0.f; acc[i][3]=0.f; }

    int tileA = lane >> 3;
    int rlA   = ((tileA & 1) << 3) + (lane & 7);
    int thiA  = tileA >> 1;
    int r7A   = lane & 7;
    uint32_t aRowByte = (uint32_t)((wm * 64 + rlA) * 128);
    int l16 = lane & 15;
    int tB  = l16 >> 3;
    int rlB = l16 & 7;
    uint32_t bRowByte = (uint32_t)((wn * 32 + rlB) * 128);

    VG_ISSUE(0, 0);
    int buf = 0;
    const int NST = HID / 32;
    for (int s = 0; s < NST; s++) {
        if (s + 1 < NST) { VG_ISSUE(s + 1, buf ^ 1); CP_WAIT1(); }
        else             { CP_WAIT0(); }
        __syncthreads();
        uint32_t Ab = sbase + (uint32_t)buf * 16384u;
        uint32_t Bb = sbase + 32768u + (uint32_t)buf * 16384u;
        #pragma unroll
        for (int ss = 0; ss < 4; ss++) {
            uint32_t b0[4], b1[4];
            #pragma unroll
            for (int nt = 0; nt < 4; nt++) {
                uint32_t addr = Bb + bRowByte + (uint32_t)(nt * 1024)
                              + (uint32_t)(((ss * 2 + tB) ^ rlB) << 4);
                LDMX2(b0[nt], b1[nt], addr);
            }
            #pragma unroll
            for (int mt = 0; mt < 4; mt++) {
                uint32_t a0, a1, a2, a3;
                uint32_t addr = Ab + aRowByte + (uint32_t)(mt * 2048)
                              + (uint32_t)(((ss * 2 + thiA) ^ r7A) << 4);
                LDMX4(a0, a1, a2, a3, addr);
                #pragma unroll
                for (int nt = 0; nt < 4; nt++)
                    MMA_TF32(acc[mt * 4 + nt], a0, a1, a2, a3, b0[nt], b1[nt]);
            }
        }
        __syncthreads();
        buf ^= 1;
    }

    // epilogue
    int rr = lane >> 2, cc = (lane & 3) * 2;
    #pragma unroll
    for (int mt = 0; mt < 4; mt++) {
        int m = m0 + wm * 64 + mt * 16 + rr;
        #pragma unroll
        for (int nt = 0; nt < 4; nt++) {
            int n = n0 + wn * 32 + nt * 8 + cc;
            const float* d = acc[mt * 4 + nt];
            float2 bb = *(const float2*)(vb + n);
            float2 o0 = make_float2(d[0] + bb.x, d[1] + bb.y);
            float2 o1 = make_float2(d[2] + bb.x, d[3] + bb.y);
            *(float2*)(out + (size_t)m * VOC + n) = o0;
            *(float2*)(out + (size_t)(m + 8) * VOC + n) = o1;
        }
    }
#undef VG_ISSUE
}

// ---------------- launch ----------------
extern "C" void kernel_launch(void* const* d_in, const int* in_sizes, int n_in,
                              void* d_out, int out_size) {
    const int*   x    = (const int*)  d_in[0];
    const float* emb  = (const float*)d_in[1];
    const float* gw   = (const float*)d_in[2];
    const float* gb   = (const float*)d_in[3];
    const float* ew   = (const float*)d_in[4];
    const float* eb   = (const float*)d_in[5];
    const float* ela  = (const float*)d_in[6];
    const float* elb  = (const float*)d_in[7];
    const float* cv   = (const float*)d_in[8];
    const float* cimp = (const float*)d_in[9];
    const float* cla  = (const float*)d_in[10];
    const float* clb  = (const float*)d_in[11];
    const float* vw   = (const float*)d_in[12];
    const float* vb   = (const float*)d_in[13];
    float* out = (float*)d_out;

    cudaFuncSetAttribute(k_egemm2, cudaFuncAttributeMaxDynamicSharedMemorySize, 49152);
    cudaFuncSetAttribute(k_vgemm2, cudaFuncAttributeMaxDynamicSharedMemorySize, 65536);

    k_zero<<<1, 32>>>();
    k_wmodT<<<dim3(HID / 64, HID / 64, NEXP), 256>>>(ew, ela, elb);
    k_select<<<NEXP, 256>>>(cimp);
    k_sumsel<<<dim3(HID / 256, NEXP, 8), 256>>>(cv);
    k_cvec<<<NEXP, 256>>>(cla, clb, eb);
    k_route<<<NTOK, 256>>>(x, emb, gw, gb);
    k_egemm2<<<dim3(HID / 128, NTOK / 64, NEXP), 256, 49152>>>();
    k_aprep<<<NTOK, 256>>>();
    k_wt<<<dim3(VOC / 64, HID / 64), 256>>>(vw);
    k_vgemm2<<<dim3(NTOK / 128, VOC / 128), 256, 65536>>>(vb, out);
}

// round 13
// speedup vs baseline: 6.1110x; 1.4842x over previous
#include <cuda_runtime.h>
#include <cuda_fp16.h>
#include <stdint.h>

// Problem constants
#define NTOK 2048      // B*S = 2*1024
#define HID  1024
#define NEXP 8
#define VOC  32000
#define KVC  2048
#define LSCALE 0.25f   // ALPHA / RANK

// ---------------- scratch (device globals; no allocations) ----------------
__device__ __half g_hbuf[NTOK * HID];             // fp16 embedded tokens   4 MB
__device__ __half g_wmod[NEXP * HID * HID];       // fp16 (W+la@lb*s)^T    16 MB [e][f][h]
__device__ float  g_cvec[NEXP * HID];             // cache_vec + expert_b
__device__ float  g_partial[2 * NTOK * HID];      // per-slot outputs      16 MB
__device__ __half g_abuf[NTOK * HID];             // fp16(p0+p1)            4 MB
__device__ __half g_wt[(size_t)VOC * HID];        // fp16(vocab_w^T)       64 MB [n][k]
__device__ int    g_count[NEXP];
__device__ unsigned int g_plist[NEXP * NTOK];     // token | slot<<16
__device__ float  g_pw[NEXP * NTOK];
__device__ unsigned char g_self[NEXP * KVC];
__device__ float  g_msum_part[NEXP * 8 * HID];

__device__ __forceinline__ uint32_t smem_u32(const void* p) {
    uint32_t a;
    asm("{ .reg .u64 t; cvta.to.shared.u64 t, %1; cvt.u32.u64 %0, t; }" : "=r"(a) : "l"(p));
    return a;
}
__device__ __forceinline__ void cp16(uint32_t dst, const void* src) {
    asm volatile("cp.async.cg.shared.global [%0], [%1], 16;" :: "r"(dst), "l"(src) : "memory");
}
#define CP_COMMIT() asm volatile("cp.async.commit_group;" ::: "memory")
#define CP_WAIT1()  asm volatile("cp.async.wait_group 1;" ::: "memory")
#define CP_WAIT0()  asm volatile("cp.async.wait_group 0;" ::: "memory")

#define LDMX4(a0,a1,a2,a3,addr) \
    asm volatile("ldmatrix.sync.aligned.m8n8.x4.shared.b16 {%0,%1,%2,%3}, [%4];" \
        : "=r"(a0), "=r"(a1), "=r"(a2), "=r"(a3) : "r"(addr))
#define LDMX2(b0,b1,addr) \
    asm volatile("ldmatrix.sync.aligned.m8n8.x2.shared.b16 {%0,%1}, [%2];" \
        : "=r"(b0), "=r"(b1) : "r"(addr))
#define MMA_F16(d, A0,A1,A2,A3, B0,B1) \
    asm volatile("mma.sync.aligned.m16n8k16.row.col.f32.f16.f16.f32 " \
        "{%0,%1,%2,%3}, {%4,%5,%6,%7}, {%8,%9}, {%0,%1,%2,%3};" \
        : "+f"((d)[0]), "+f"((d)[1]), "+f"((d)[2]), "+f"((d)[3]) \
        : "r"(A0), "r"(A1), "r"(A2), "r"(A3), "r"(B0), "r"(B1))

// ---------------- k0: zero routing counters ----------------
__global__ void k_zero() {
    if (threadIdx.x < NEXP) g_count[threadIdx.x] = 0;
}

// ---------------- k_wmodT: g_wmod[e][f][h] = fp16(ew[e][h][f] + s*la@lb) ----------------
// grid (HID/64 f-tiles, HID/64 h-tiles, NEXP), block 256
__global__ void k_wmodT(const float* __restrict__ ew, const float* __restrict__ la,
                        const float* __restrict__ lb) {
    __shared__ float ts[64][65];
    int e = blockIdx.z;
    int n0 = blockIdx.x * 64, k0 = blockIdx.y * 64;
    int tid = threadIdx.x;
    const float* lbe = lb + (size_t)e * 4 * HID;
    #pragma unroll
    for (int r = 0; r < 16; r++) {
        int idx = tid + r * 256;
        int kk = idx / 64, nn = idx % 64;
        int h = k0 + kk, f = n0 + nn;
        const float* lar = la + ((size_t)e * HID + h) * 4;
        float v = ew[((size_t)e * HID + h) * HID + f]
                + LSCALE * (lar[0] * lbe[f] + lar[1] * lbe[HID + f]
                           + lar[2] * lbe[2 * HID + f] + lar[3] * lbe[3 * HID + f]);
        ts[kk][nn] = v;
    }
    __syncthreads();
    #pragma unroll
    for (int r = 0; r < 8; r++) {
        int idx = tid + r * 256;
        int nn = idx >> 5, kp = idx & 31;
        __half2 hp = __floats2half2_rn(ts[kp * 2][nn], ts[kp * 2 + 1][nn]);
        *(__half2*)(g_wmod + ((size_t)e * HID + n0 + nn) * HID + k0 + kp * 2) = hp;
    }
}

// ---------------- k2a: exact top-k selection via 32-bit greedy threshold ----------------
__global__ void k_select(const float* __restrict__ imp) {
    int e = blockIdx.x;
    int n = KVC - 128 * e;
    int k = n / 2;
    __shared__ unsigned int sv[KVC];
    __shared__ int red[256];
    int tid = threadIdx.x;
    for (int i = tid; i < n; i += 256) sv[i] = __float_as_uint(imp[e * KVC + i]);
    __syncthreads();

    unsigned int T = 0;
    for (int bit = 31; bit >= 0; --bit) {
        unsigned int cand = T | (1u << bit);
        int c = 0;
        for (int i = tid; i < n; i += 256) c += (sv[i] >= cand);
        red[tid] = c; __syncthreads();
        for (int s = 128; s > 0; s >>= 1) { if (tid < s) red[tid] += red[tid + s]; __syncthreads(); }
        int cnt = red[0];
        __syncthreads();
        if (cnt >= k) T = cand;
    }
    int c = 0;
    for (int i = tid; i < n; i += 256) c += (sv[i] > T);
    red[tid] = c; __syncthreads();
    for (int s = 128; s > 0; s >>= 1) { if (tid < s) red[tid] += red[tid + s]; __syncthreads(); }
    int g = red[0];
    __syncthreads();
    for (int i = tid; i < n; i += 256) g_self[e * KVC + i] = (sv[i] > T) ? 1 : 0;
    __syncthreads();
    if (tid == 0) {
        int extra = k - g;
        for (int i = 0; i < n && extra > 0; i++) {
            if (sv[i] == T) { g_self[e * KVC + i] = 1; extra--; }
        }
    }
}

// ---------------- k2b: masked column partial sums (deterministic 2-stage) ----------------
__global__ void k_sumsel(const float* __restrict__ cv) {
    int e = blockIdx.y, z = blockIdx.z;
    int col = blockIdx.x * 256 + threadIdx.x;
    int n = KVC - 128 * e;
    int r0 = z * 256;
    int r1 = min(r0 + 256, n);
    __shared__ unsigned char fl[256];
    fl[threadIdx.x] = (r0 + (int)threadIdx.x < r1) ? g_self[e * KVC + r0 + threadIdx.x] : 0;
    __syncthreads();
    float acc = 0.f;
    const float* base = cv + (size_t)e * KVC * HID + (size_t)r0 * HID + col;
    for (int i = 0; i < r1 - r0; i++)
        if (fl[i]) acc += base[(size_t)i * HID];
    g_msum_part[(size_t)(e * 8 + z) * HID + col] = acc;
}

// ---------------- k2c: cache vec = m + (m@la)@lb*s + expert_b ----------------
__global__ void k_cvec(const float* __restrict__ la, const float* __restrict__ lb,
                       const float* __restrict__ eb) {
    int e = blockIdx.x, tid = threadIdx.x;
    __shared__ float m[HID];
    __shared__ float red[4 * 256];
    int k = (KVC - 128 * e) / 2;
    float invk = 1.f / (float)k;
    for (int f = tid; f < HID; f += 256) {
        float s = 0.f;
        #pragma unroll
        for (int z = 0; z < 8; z++) s += g_msum_part[(size_t)(e * 8 + z) * HID + f];
        m[f] = s * invk;
    }
    __syncthreads();
    float u[4] = {0.f, 0.f, 0.f, 0.f};
    for (int f = tid; f < HID; f += 256) {
        float mv = m[f];
        const float* lr = la + ((size_t)e * HID + f) * 4;
        u[0] += mv * lr[0]; u[1] += mv * lr[1]; u[2] += mv * lr[2]; u[3] += mv * lr[3];
    }
    #pragma unroll
    for (int r = 0; r < 4; r++) red[r * 256 + tid] = u[r];
    __syncthreads();
    for (int s = 128; s > 0; s >>= 1) {
        if (tid < s)
            #pragma unroll
            for (int r = 0; r < 4; r++) red[r * 256 + tid] += red[r * 256 + tid + s];
        __syncthreads();
    }
    float u0 = red[0], u1 = red[256], u2 = red[512], u3 = red[768];
    const float* lbe = lb + (size_t)e * 4 * HID;
    for (int f = tid; f < HID; f += 256) {
        g_cvec[e * HID + f] = m[f]
            + LSCALE * (u0 * lbe[f] + u1 * lbe[HID + f] + u2 * lbe[2 * HID + f] + u3 * lbe[3 * HID + f])
            + eb[e * HID + f];
    }
}

// ---------------- k3: embedding gather + gate + top-2 routing ----------------
// g_hbuf rows stored fp16 (consumed only by the fp16 expert GEMM)
__global__ void k_route(const int* __restrict__ x, const float* __restrict__ emb,
                        const float* __restrict__ gw, const float* __restrict__ gb) {
    int t = blockIdx.x, tid = threadIdx.x;
    __shared__ float hs[HID];
    __shared__ float sred[8][8];
    const float* er = emb + (size_t)x[t] * HID;
    float4* hs4 = (float4*)hs;
    __half2* hb2 = (__half2*)(g_hbuf + (size_t)t * HID);
    for (int i = tid; i < HID / 4; i += 256) {
        float4 v = ((const float4*)er)[i];
        hs4[i] = v;
        hb2[2 * i]     = __floats2half2_rn(v.x, v.y);
        hb2[2 * i + 1] = __floats2half2_rn(v.z, v.w);
    }
    __syncthreads();
    float p[8] = {0.f, 0.f, 0.f, 0.f, 0.f, 0.f, 0.f, 0.f};
    for (int i = tid; i < HID; i += 256) {
        float hv = hs[i];
        const float* g = gw + (size_t)i * 8;
        #pragma unroll
        for (int e2 = 0; e2 < 8; e2++) p[e2] += hv * g[e2];
    }
    #pragma unroll
    for (int off = 16; off > 0; off >>= 1)
        #pragma unroll
        for (int e2 = 0; e2 < 8; e2++) p[e2] += __shfl_down_sync(0xffffffffu, p[e2], off);
    int warp = tid / 32, lane = tid % 32;
    if (lane == 0)
        #pragma unroll
        for (int e2 = 0; e2 < 8; e2++) sred[e2][warp] = p[e2];
    __syncthreads();
    if (tid == 0) {
        float lg[8];
        #pragma unroll
        for (int e2 = 0; e2 < 8; e2++) {
            float s = 0.f;
            #pragma unroll
            for (int w = 0; w < 8; w++) s += sred[e2][w];
            lg[e2] = s + gb[e2];
        }
        int i1 = 0;
        #pragma unroll
        for (int e2 = 1; e2 < 8; e2++) if (lg[e2] > lg[i1]) i1 = e2;
        int i2 = -1;
        #pragma unroll
        for (int e2 = 0; e2 < 8; e2++) {
            if (e2 == i1) continue;
            if (i2 < 0 || lg[e2] > lg[i2]) i2 = e2;
        }
        float w1 = 1.f / (1.f + expf(lg[i2] - lg[i1]));
        float w2 = 1.f - w1;
        int p1 = atomicAdd(&g_count[i1], 1);
        g_plist[i1 * NTOK + p1] = (unsigned)t;
        g_pw[i1 * NTOK + p1] = w1;
        int p2 = atomicAdd(&g_count[i2], 1);
        g_plist[i2 * NTOK + p2] = (unsigned)t | (1u << 16);
        g_pw[i2 * NTOK + p2] = w2;
    }
}

// ---------------- k_egemm2: per-expert gathered fp16 mma GEMM, 64x128 tile ----------------
// grid (HID/128, NTOK/64, NEXP), block 256 (8 warps = 2m x 4n, warp tile 32x32)
// smem (dynamic, 48KB): 2 stages x (A[64][64]h 8KB + B[128][64]h 16KB); K-chunk 64
__global__ void __launch_bounds__(256, 2) k_egemm2() {
    extern __shared__ float esm[];
    __shared__ unsigned int stok[64];
    __shared__ float swt[64];

    int e = blockIdx.z;
    int cnt = g_count[e];
    int m0 = blockIdx.y * 64;
    if (m0 >= cnt) return;
    int n0 = blockIdx.x * 128;

    int tid = threadIdx.x;
    int lane = tid & 31, wid = tid >> 5;
    int wm = wid >> 2, wn = wid & 3;
    uint32_t sbase = smem_u32(esm);

    if (tid < 64) {
        int p = m0 + tid;
        if (p < cnt) { stok[tid] = g_plist[e * NTOK + p]; swt[tid] = g_pw[e * NTOK + p]; }
        else         { stok[tid] = 0u;                    swt[tid] = 0.f; }
    }
    __syncthreads();

    const __half* wmT = g_wmod + (size_t)e * HID * HID;

#define EG_ISSUE(STAGE, BUF) do {                                              \
    int k0 = (STAGE) * 64;                                                     \
    _Pragma("unroll") for (int j = 0; j < 2; j++) {                            \
        int idx = tid + j * 256;                                               \
        int row = idx >> 3, slot = idx & 7;                                    \
        int tok = (int)(stok[row] & 0xffffu);                                  \
        uint32_t dst = sbase + (uint32_t)(BUF) * 24576u                        \
                     + (uint32_t)(row * 128 + ((slot ^ (row & 7)) << 4));      \
        cp16(dst, g_hbuf + (size_t)tok * HID + k0 + slot * 8);                 \
    }                                                                          \
    _Pragma("unroll") for (int j = 0; j < 4; j++) {                            \
        int idx = tid + j * 256;                                               \
        int row = idx >> 3, slot = idx & 7;                                    \
        uint32_t dst = sbase + 8192u + (uint32_t)(BUF) * 24576u                \
                     + (uint32_t)(row * 128 + ((slot ^ (row & 7)) << 4));      \
        cp16(dst, wmT + (size_t)(n0 + row) * HID + k0 + slot * 8);             \
    }                                                                          \
    CP_COMMIT();                                                               \
} while (0)

    float acc[8][4];
    #pragma unroll
    for (int i = 0; i < 8; i++) { acc[i][0]=0.f; acc[i][1]=0.f; acc[i][2]=0.f; acc[i][3]=0.f; }

    // ldmatrix per-lane constants (fp16 fragments)
    int tileA = lane >> 3;
    int rlA   = ((tileA & 1) << 3) + (lane & 7);
    int thiA  = tileA >> 1;
    int r7A   = lane & 7;
    uint32_t aRowByte = (uint32_t)((wm * 32 + rlA) * 128);
    int l16 = lane & 15;
    int tB  = l16 >> 3;
    int rlB = l16 & 7;
    uint32_t bRowByte = (uint32_t)((wn * 32 + rlB) * 128);

    EG_ISSUE(0, 0);
    int buf = 0;
    const int NST = HID / 64;
    for (int s = 0; s < NST; s++) {
        if (s + 1 < NST) { EG_ISSUE(s + 1, buf ^ 1); CP_WAIT1(); }
        else             { CP_WAIT0(); }
        __syncthreads();
        uint32_t Ab = sbase + (uint32_t)buf * 24576u;
        uint32_t Bb = sbase + 8192u + (uint32_t)buf * 24576u;
        #pragma unroll
        for (int ks = 0; ks < 4; ks++) {
            uint32_t b0[4], b1[4];
            #pragma unroll
            for (int nt = 0; nt < 4; nt++) {
                uint32_t addr = Bb + bRowByte + (uint32_t)(nt * 1024)
                              + (uint32_t)(((ks * 2 + tB) ^ rlB) << 4);
                LDMX2(b0[nt], b1[nt], addr);
            }
            #pragma unroll
            for (int mt = 0; mt < 2; mt++) {
                uint32_t a0, a1, a2, a3;
                uint32_t addr = Ab + aRowByte + (uint32_t)(mt * 2048)
                              + (uint32_t)(((ks * 2 + thiA) ^ r7A) << 4);
                LDMX4(a0, a1, a2, a3, addr);
                #pragma unroll
                for (int nt = 0; nt < 4; nt++)
                    MMA_F16(acc[mt * 4 + nt], a0, a1, a2, a3, b0[nt], b1[nt]);
            }
        }
        __syncthreads();
        buf ^= 1;
    }

    // epilogue: out[slot][tok][n] = w * (acc + cvec)
    int rr = lane >> 2, cc = (lane & 3) * 2;
    #pragma unroll
    for (int mt = 0; mt < 2; mt++) {
        #pragma unroll
        for (int half = 0; half < 2; half++) {
            int ml = wm * 32 + mt * 16 + rr + half * 8;
            if (m0 + ml >= cnt) continue;
            unsigned int pk = stok[ml];
            int tok = (int)(pk & 0xffffu), slot = (int)(pk >> 16);
            float w = swt[ml];
            float* outp = g_partial + (size_t)slot * NTOK * HID + (size_t)tok * HID;
            #pragma unroll
            for (int nt = 0; nt < 4; nt++) {
                int n = n0 + wn * 32 + nt * 8 + cc;
                const float* d = acc[mt * 4 + nt];
                float cv0 = g_cvec[e * HID + n], cv1 = g_cvec[e * HID + n + 1];
                float2 o;
                o.x = w * (d[half * 2 + 0] + cv0);
                o.y = w * (d[half * 2 + 1] + cv1);
                *(float2*)(outp + n) = o;
            }
        }
    }
#undef EG_ISSUE
}

// ---------------- k_aprep: A = fp16(p0 + p1) ----------------
__global__ void k_aprep() {
    int m = blockIdx.x;
    const float4* p0 = (const float4*)(g_partial + (size_t)m * HID);
    const float4* p1 = (const float4*)(g_partial + (size_t)NTOK * HID + (size_t)m * HID);
    __half2* a2 = (__half2*)(g_abuf + (size_t)m * HID);
    int i = threadIdx.x;
    float4 v0 = p0[i], v1 = p1[i];
    a2[2 * i]     = __floats2half2_rn(v0.x + v1.x, v0.y + v1.y);
    a2[2 * i + 1] = __floats2half2_rn(v0.z + v1.z, v0.w + v1.w);
}

// ---------------- k_wt: g_wt[n][k] = fp16(vocab_w[k][n]) ----------------
// grid (VOC/64, HID/64), block 256
__global__ void k_wt(const float* __restrict__ vw) {
    __shared__ float ts[64][65];
    int n0 = blockIdx.x * 64, k0 = blockIdx.y * 64;
    int tid = threadIdx.x;
    #pragma unroll
    for (int r = 0; r < 16; r++) {
        int idx = tid + r * 256;
        int kk = idx / 64, nn = idx % 64;
        ts[kk][nn] = vw[(size_t)(k0 + kk) * VOC + n0 + nn];
    }
    __syncthreads();
    #pragma unroll
    for (int r = 0; r < 8; r++) {
        int idx = tid + r * 256;
        int nn = idx >> 5, kp = idx & 31;
        __half2 hp = __floats2half2_rn(ts[kp * 2][nn], ts[kp * 2 + 1][nn]);
        *(__half2*)(g_wt + (size_t)(n0 + nn) * HID + k0 + kp * 2) = hp;
    }
}

// ---------------- k_vgemm2: fp16 mma GEMM, 128x128 tile, 3-stage cp.async + ldmatrix ----------------
// grid (NTOK/128=16, VOC/128=250), block 256 (8 warps = 2m x 4n, warp tile 64x32)
// smem (dynamic, 96KB): 3 stages x (A[128][64]h 16KB + B[128][64]h 16KB); K-chunk 64
__global__ void __launch_bounds__(256, 2) k_vgemm2(const float* __restrict__ vb,
                                                   float* __restrict__ out) {
    extern __shared__ float vsm[];
    int tid = threadIdx.x;
    int lane = tid & 31, wid = tid >> 5;
    int wm = wid >> 2, wn = wid & 3;
    int m0 = blockIdx.x * 128, n0 = blockIdx.y * 128;
    const __half* Ag = g_abuf + (size_t)m0 * HID;
    const __half* Bg = g_wt   + (size_t)n0 * HID;
    uint32_t sbase = smem_u32(vsm);

#define VG_ISSUE(STAGE, BUF) do {                                              \
    int k0 = (STAGE) * 64;                                                     \
    _Pragma("unroll") for (int j = 0; j < 4; j++) {                            \
        int idx = tid + j * 256;                                               \
        int row = idx >> 3, slot = idx & 7;                                    \
        uint32_t so = (uint32_t)(row * 128 + ((slot ^ (row & 7)) << 4));       \
        cp16(sbase + (uint32_t)(BUF) * 32768u + so,                            \
             Ag + (size_t)row * HID + k0 + slot * 8);                          \
        cp16(sbase + 16384u + (uint32_t)(BUF) * 32768u + so,                   \
             Bg + (size_t)row * HID + k0 + slot * 8);                          \
    }                                                                          \
    CP_COMMIT();                                                               \
} while (0)

    float acc[16][4];
    #pragma unroll
    for (int i = 0; i < 16; i++) { acc[i][0]=0.f; acc[i][1]=0.f; acc[i][2]=0.f; acc[i][3]=0.f; }

    int tileA = lane >> 3;
    int rlA   = ((tileA & 1) << 3) + (lane & 7);
    int thiA  = tileA >> 1;
    int r7A   = lane & 7;
    uint32_t aRowByte = (uint32_t)((wm * 64 + rlA) * 128);
    int l16 = lane & 15;
    int tB  = l16 >> 3;
    int rlB = l16 & 7;
    uint32_t bRowByte = (uint32_t)((wn * 32 + rlB) * 128);

    const int NST = HID / 64;                      // 16 chunks
    VG_ISSUE(0, 0);
    VG_ISSUE(1, 1);
    int buf = 0;                                   // buf = s % 3
    for (int s = 0; s < NST; s++) {
        if (s + 1 < NST) CP_WAIT1(); else CP_WAIT0();
        __syncthreads();                           // stage s ready + all warps done with s-1
        if (s + 2 < NST) {
            int nb = buf + 2; if (nb >= 3) nb -= 3;
            VG_ISSUE(s + 2, nb);                   // overwrites buffer of stage s-1 (safe)
        }
        uint32_t Ab = sbase + (uint32_t)buf * 32768u;
        uint32_t Bb = Ab + 16384u;
        #pragma unroll
        for (int ks = 0; ks < 4; ks++) {
            uint32_t b0[4], b1[4];
            #pragma unroll
            for (int nt = 0; nt < 4; nt++) {
                uint32_t addr = Bb + bRowByte + (uint32_t)(nt * 1024)
                              + (uint32_t)(((ks * 2 + tB) ^ rlB) << 4);
                LDMX2(b0[nt], b1[nt], addr);
            }
            #pragma unroll
            for (int mt = 0; mt < 4; mt++) {
                uint32_t a0, a1, a2, a3;
                uint32_t addr = Ab + aRowByte + (uint32_t)(mt * 2048)
                              + (uint32_t)(((ks * 2 + thiA) ^ r7A) << 4);
                LDMX4(a0, a1, a2, a3, addr);
                #pragma unroll
                for (int nt = 0; nt < 4; nt++)
                    MMA_F16(acc[mt * 4 + nt], a0, a1, a2, a3, b0[nt], b1[nt]);
            }
        }
        buf++; if (buf >= 3) buf -= 3;
    }

    // epilogue
    int rr = lane >> 2, cc = (lane & 3) * 2;
    #pragma unroll
    for (int mt = 0; mt < 4; mt++) {
        int m = m0 + wm * 64 + mt * 16 + rr;
        #pragma unroll
        for (int nt = 0; nt < 4; nt++) {
            int n = n0 + wn * 32 + nt * 8 + cc;
            const float* d = acc[mt * 4 + nt];
            float2 bb = *(const float2*)(vb + n);
            float2 o0 = make_float2(d[0] + bb.x, d[1] + bb.y);
            float2 o1 = make_float2(d[2] + bb.x, d[3] + bb.y);
            *(float2*)(out + (size_t)m * VOC + n) = o0;
            *(float2*)(out + (size_t)(m + 8) * VOC + n) = o1;
        }
    }
#undef VG_ISSUE
}

// ---------------- launch ----------------
extern "C" void kernel_launch(void* const* d_in, const int* in_sizes, int n_in,
                              void* d_out, int out_size) {
    const int*   x    = (const int*)  d_in[0];
    const float* emb  = (const float*)d_in[1];
    const float* gw   = (const float*)d_in[2];
    const float* gb   = (const float*)d_in[3];
    const float* ew   = (const float*)d_in[4];
    const float* eb   = (const float*)d_in[5];
    const float* ela  = (const float*)d_in[6];
    const float* elb  = (const float*)d_in[7];
    const float* cv   = (const float*)d_in[8];
    const float* cimp = (const float*)d_in[9];
    const float* cla  = (const float*)d_in[10];
    const float* clb  = (const float*)d_in[11];
    const float* vw   = (const float*)d_in[12];
    const float* vb   = (const float*)d_in[13];
    float* out = (float*)d_out;

    cudaFuncSetAttribute(k_egemm2, cudaFuncAttributeMaxDynamicSharedMemorySize, 49152);
    cudaFuncSetAttribute(k_vgemm2, cudaFuncAttributeMaxDynamicSharedMemorySize, 98304);

    k_zero<<<1, 32>>>();
    k_wmodT<<<dim3(HID / 64, HID / 64, NEXP), 256>>>(ew, ela, elb);
    k_select<<<NEXP, 256>>>(cimp);
    k_sumsel<<<dim3(HID / 256, NEXP, 8), 256>>>(cv);
    k_cvec<<<NEXP, 256>>>(cla, clb, eb);
    k_route<<<NTOK, 256>>>(x, emb, gw, gb);
    k_egemm2<<<dim3(HID / 128, NTOK / 64, NEXP), 256, 49152>>>();
    k_aprep<<<NTOK, 256>>>();
    k_wt<<<dim3(VOC / 64, HID / 64), 256>>>(vw);
    k_vgemm2<<<dim3(NTOK / 128, VOC / 128), 256, 98304>>>(vb, out);
}

// round 14
// speedup vs baseline: 6.4070x; 1.0484x over previous
#include <cuda_runtime.h>
#include <cuda_fp16.h>
#include <stdint.h>

// Problem constants
#define NTOK 2048      // B*S = 2*1024
#define HID  1024
#define NEXP 8
#define VOC  32000
#define KVC  2048
#define LSCALE 0.25f   // ALPHA / RANK

// ---------------- scratch (device globals; no allocations) ----------------
__device__ __half g_hbuf[NTOK * HID];             // fp16 embedded tokens   4 MB
__device__ __half g_wmod[NEXP * HID * HID];       // fp16 (W+la@lb*s)^T    16 MB [e][f][h]
__device__ float  g_cvec[NEXP * HID];             // cache_vec + expert_b
__device__ float  g_partial[2 * NTOK * HID];      // per-slot outputs      16 MB
__device__ __half g_abuf[NTOK * HID];             // fp16(p0+p1)            4 MB
__device__ __half g_wt[(size_t)VOC * HID];        // fp16(vocab_w^T)       64 MB [n][k]
__device__ int    g_count[NEXP];
__device__ unsigned int g_plist[NEXP * NTOK];     // token | slot<<16
__device__ float  g_pw[NEXP * NTOK];
__device__ unsigned char g_self[NEXP * KVC];
__device__ float  g_msum_part[NEXP * 8 * HID];

__device__ __forceinline__ uint32_t smem_u32(const void* p) {
    uint32_t a;
    asm("{ .reg .u64 t; cvta.to.shared.u64 t, %1; cvt.u32.u64 %0, t; }" : "=r"(a) : "l"(p));
    return a;
}
__device__ __forceinline__ void cp16(uint32_t dst, const void* src) {
    asm volatile("cp.async.cg.shared.global [%0], [%1], 16;" :: "r"(dst), "l"(src) : "memory");
}
#define CP_COMMIT() asm volatile("cp.async.commit_group;" ::: "memory")
#define CP_WAIT1()  asm volatile("cp.async.wait_group 1;" ::: "memory")
#define CP_WAIT0()  asm volatile("cp.async.wait_group 0;" ::: "memory")

#define LDMX4(a0,a1,a2,a3,addr) \
    asm volatile("ldmatrix.sync.aligned.m8n8.x4.shared.b16 {%0,%1,%2,%3}, [%4];" \
        : "=r"(a0), "=r"(a1), "=r"(a2), "=r"(a3) : "r"(addr))
#define LDMX2(b0,b1,addr) \
    asm volatile("ldmatrix.sync.aligned.m8n8.x2.shared.b16 {%0,%1}, [%2];" \
        : "=r"(b0), "=r"(b1) : "r"(addr))
#define MMA_F16(d, A0,A1,A2,A3, B0,B1) \
    asm volatile("mma.sync.aligned.m16n8k16.row.col.f32.f16.f16.f32 " \
        "{%0,%1,%2,%3}, {%4,%5,%6,%7}, {%8,%9}, {%0,%1,%2,%3};" \
        : "+f"((d)[0]), "+f"((d)[1]), "+f"((d)[2]), "+f"((d)[3]) \
        : "r"(A0), "r"(A1), "r"(A2), "r"(A3), "r"(B0), "r"(B1))

// ---------------- k0: zero routing counters ----------------
__global__ void k_zero() {
    if (threadIdx.x < NEXP) g_count[threadIdx.x] = 0;
}

// ---------------- k_prep: fused select | wmodT | route | wt ----------------
// flattened grid: [0,8) select, [8,2056) wmodT, [2056,4104) route, [4104,12104) wt
#define PREP_SEL0   0
#define PREP_WMOD0  8
#define PREP_ROUTE0 (PREP_WMOD0 + 2048)
#define PREP_WT0    (PREP_ROUTE0 + NTOK)
#define PREP_BLOCKS (PREP_WT0 + 8000)

__global__ void __launch_bounds__(256) k_prep(
    const float* __restrict__ ew, const float* __restrict__ la, const float* __restrict__ lb,
    const float* __restrict__ imp,
    const int* __restrict__ x, const float* __restrict__ emb,
    const float* __restrict__ gw, const float* __restrict__ gb,
    const float* __restrict__ vw)
{
    __shared__ float ts[64][65];          // wmodT / wt transpose buffer
    __shared__ unsigned int sv[KVC];      // select
    __shared__ int redi[256];             // select reduce
    __shared__ float hs[HID];             // route
    __shared__ float sred[8][8];          // route reduce

    int bid = blockIdx.x;
    int tid = threadIdx.x;

    if (bid < PREP_WMOD0) {
        // ===== k_select (block = expert) =====
        int e = bid;
        int n = KVC - 128 * e;
        int k = n / 2;
        for (int i = tid; i < n; i += 256) sv[i] = __float_as_uint(imp[e * KVC + i]);
        __syncthreads();
        unsigned int T = 0;
        for (int bit = 31; bit >= 0; --bit) {
            unsigned int cand = T | (1u << bit);
            int c = 0;
            for (int i = tid; i < n; i += 256) c += (sv[i] >= cand);
            redi[tid] = c; __syncthreads();
            for (int s = 128; s > 0; s >>= 1) { if (tid < s) redi[tid] += redi[tid + s]; __syncthreads(); }
            int cnt = redi[0];
            __syncthreads();
            if (cnt >= k) T = cand;
        }
        int c = 0;
        for (int i = tid; i < n; i += 256) c += (sv[i] > T);
        redi[tid] = c; __syncthreads();
        for (int s = 128; s > 0; s >>= 1) { if (tid < s) redi[tid] += redi[tid + s]; __syncthreads(); }
        int g = redi[0];
        __syncthreads();
        for (int i = tid; i < n; i += 256) g_self[e * KVC + i] = (sv[i] > T) ? 1 : 0;
        __syncthreads();
        if (tid == 0) {
            int extra = k - g;
            for (int i = 0; i < n && extra > 0; i++) {
                if (sv[i] == T) { g_self[e * KVC + i] = 1; extra--; }
            }
        }
    } else if (bid < PREP_ROUTE0) {
        // ===== k_wmodT: g_wmod[e][f][h] = fp16(ew[e][h][f] + s*la@lb) =====
        int b = bid - PREP_WMOD0;
        int e = b >> 8;                      // /256
        int n0 = (b & 15) * 64;              // f tile
        int k0 = ((b >> 4) & 15) * 64;       // h tile
        const float* lbe = lb + (size_t)e * 4 * HID;
        #pragma unroll
        for (int r = 0; r < 16; r++) {
            int idx = tid + r * 256;
            int kk = idx / 64, nn = idx % 64;
            int h = k0 + kk, f = n0 + nn;
            const float* lar = la + ((size_t)e * HID + h) * 4;
            float v = ew[((size_t)e * HID + h) * HID + f]
                    + LSCALE * (lar[0] * lbe[f] + lar[1] * lbe[HID + f]
                               + lar[2] * lbe[2 * HID + f] + lar[3] * lbe[3 * HID + f]);
            ts[kk][nn] = v;
        }
        __syncthreads();
        #pragma unroll
        for (int r = 0; r < 8; r++) {
            int idx = tid + r * 256;
            int nn = idx >> 5, kp = idx & 31;
            __half2 hp = __floats2half2_rn(ts[kp * 2][nn], ts[kp * 2 + 1][nn]);
            *(__half2*)(g_wmod + ((size_t)e * HID + n0 + nn) * HID + k0 + kp * 2) = hp;
        }
    } else if (bid < PREP_WT0) {
        // ===== k_route (block = token) =====
        int t = bid - PREP_ROUTE0;
        const float* er = emb + (size_t)x[t] * HID;
        float4* hs4 = (float4*)hs;
        __half2* hb2 = (__half2*)(g_hbuf + (size_t)t * HID);
        for (int i = tid; i < HID / 4; i += 256) {
            float4 v = ((const float4*)er)[i];
            hs4[i] = v;
            hb2[2 * i]     = __floats2half2_rn(v.x, v.y);
            hb2[2 * i + 1] = __floats2half2_rn(v.z, v.w);
        }
        __syncthreads();
        float p[8] = {0.f, 0.f, 0.f, 0.f, 0.f, 0.f, 0.f, 0.f};
        for (int i = tid; i < HID; i += 256) {
            float hv = hs[i];
            const float* g = gw + (size_t)i * 8;
            #pragma unroll
            for (int e2 = 0; e2 < 8; e2++) p[e2] += hv * g[e2];
        }
        #pragma unroll
        for (int off = 16; off > 0; off >>= 1)
            #pragma unroll
            for (int e2 = 0; e2 < 8; e2++) p[e2] += __shfl_down_sync(0xffffffffu, p[e2], off);
        int warp = tid / 32, lane = tid % 32;
        if (lane == 0)
            #pragma unroll
            for (int e2 = 0; e2 < 8; e2++) sred[e2][warp] = p[e2];
        __syncthreads();
        if (tid == 0) {
            float lg[8];
            #pragma unroll
            for (int e2 = 0; e2 < 8; e2++) {
                float s = 0.f;
                #pragma unroll
                for (int w = 0; w < 8; w++) s += sred[e2][w];
                lg[e2] = s + gb[e2];
            }
            int i1 = 0;
            #pragma unroll
            for (int e2 = 1; e2 < 8; e2++) if (lg[e2] > lg[i1]) i1 = e2;
            int i2 = -1;
            #pragma unroll
            for (int e2 = 0; e2 < 8; e2++) {
                if (e2 == i1) continue;
                if (i2 < 0 || lg[e2] > lg[i2]) i2 = e2;
            }
            float w1 = 1.f / (1.f + expf(lg[i2] - lg[i1]));
            float w2 = 1.f - w1;
            int p1 = atomicAdd(&g_count[i1], 1);
            g_plist[i1 * NTOK + p1] = (unsigned)t;
            g_pw[i1 * NTOK + p1] = w1;
            int p2 = atomicAdd(&g_count[i2], 1);
            g_plist[i2 * NTOK + p2] = (unsigned)t | (1u << 16);
            g_pw[i2 * NTOK + p2] = w2;
        }
    } else {
        // ===== k_wt: g_wt[n][k] = fp16(vocab_w[k][n]) =====
        int b = bid - PREP_WT0;              // 8000 blocks: 500 n-tiles x 16 k-tiles
        int n0 = (b % 500) * 64, k0 = (b / 500) * 64;
        #pragma unroll
        for (int r = 0; r < 16; r++) {
            int idx = tid + r * 256;
            int kk = idx / 64, nn = idx % 64;
            ts[kk][nn] = vw[(size_t)(k0 + kk) * VOC + n0 + nn];
        }
        __syncthreads();
        #pragma unroll
        for (int r = 0; r < 8; r++) {
            int idx = tid + r * 256;
            int nn = idx >> 5, kp = idx & 31;
            __half2 hp = __floats2half2_rn(ts[kp * 2][nn], ts[kp * 2 + 1][nn]);
            *(__half2*)(g_wt + (size_t)(n0 + nn) * HID + k0 + kp * 2) = hp;
        }
    }
}

// ---------------- k2b: masked column partial sums (deterministic 2-stage) ----------------
__global__ void k_sumsel(const float* __restrict__ cv) {
    int e = blockIdx.y, z = blockIdx.z;
    int col = blockIdx.x * 256 + threadIdx.x;
    int n = KVC - 128 * e;
    int r0 = z * 256;
    int r1 = min(r0 + 256, n);
    __shared__ unsigned char fl[256];
    fl[threadIdx.x] = (r0 + (int)threadIdx.x < r1) ? g_self[e * KVC + r0 + threadIdx.x] : 0;
    __syncthreads();
    float acc = 0.f;
    const float* base = cv + (size_t)e * KVC * HID + (size_t)r0 * HID + col;
    for (int i = 0; i < r1 - r0; i++)
        if (fl[i]) acc += base[(size_t)i * HID];
    g_msum_part[(size_t)(e * 8 + z) * HID + col] = acc;
}

// ---------------- k2c: cache vec = m + (m@la)@lb*s + expert_b ----------------
__global__ void k_cvec(const float* __restrict__ la, const float* __restrict__ lb,
                       const float* __restrict__ eb) {
    int e = blockIdx.x, tid = threadIdx.x;
    __shared__ float m[HID];
    __shared__ float red[4 * 256];
    int k = (KVC - 128 * e) / 2;
    float invk = 1.f / (float)k;
    for (int f = tid; f < HID; f += 256) {
        float s = 0.f;
        #pragma unroll
        for (int z = 0; z < 8; z++) s += g_msum_part[(size_t)(e * 8 + z) * HID + f];
        m[f] = s * invk;
    }
    __syncthreads();
    float u[4] = {0.f, 0.f, 0.f, 0.f};
    for (int f = tid; f < HID; f += 256) {
        float mv = m[f];
        const float* lr = la + ((size_t)e * HID + f) * 4;
        u[0] += mv * lr[0]; u[1] += mv * lr[1]; u[2] += mv * lr[2]; u[3] += mv * lr[3];
    }
    #pragma unroll
    for (int r = 0; r < 4; r++) red[r * 256 + tid] = u[r];
    __syncthreads();
    for (int s = 128; s > 0; s >>= 1) {
        if (tid < s)
            #pragma unroll
            for (int r = 0; r < 4; r++) red[r * 256 + tid] += red[r * 256 + tid + s];
        __syncthreads();
    }
    float u0 = red[0], u1 = red[256], u2 = red[512], u3 = red[768];
    const float* lbe = lb + (size_t)e * 4 * HID;
    for (int f = tid; f < HID; f += 256) {
        g_cvec[e * HID + f] = m[f]
            + LSCALE * (u0 * lbe[f] + u1 * lbe[HID + f] + u2 * lbe[2 * HID + f] + u3 * lbe[3 * HID + f])
            + eb[e * HID + f];
    }
}

// ---------------- k_egemm3: per-expert gathered fp16 mma GEMM, 128x128 tile ----------------
// grid (HID/128=8, NTOK/128=16, NEXP), block 256 (8 warps = 2m x 4n, warp tile 64x32)
// smem (dynamic, 96KB): 3 stages x (A[128][64]h 16KB + B[128][64]h 16KB); K-chunk 64
__global__ void __launch_bounds__(256, 2) k_egemm3() {
    extern __shared__ float esm[];
    __shared__ unsigned int stok[128];
    __shared__ float swt[128];

    int e = blockIdx.z;
    int cnt = g_count[e];
    int m0 = blockIdx.y * 128;
    if (m0 >= cnt) return;
    int n0 = blockIdx.x * 128;

    int tid = threadIdx.x;
    int lane = tid & 31, wid = tid >> 5;
    int wm = wid >> 2, wn = wid & 3;
    uint32_t sbase = smem_u32(esm);

    if (tid < 128) {
        int p = m0 + tid;
        if (p < cnt) { stok[tid] = g_plist[e * NTOK + p]; swt[tid] = g_pw[e * NTOK + p]; }
        else         { stok[tid] = 0u;                    swt[tid] = 0.f; }
    }
    __syncthreads();

    const __half* wmT = g_wmod + (size_t)e * HID * HID;

#define EG_ISSUE(STAGE, BUF) do {                                              \
    int k0 = (STAGE) * 64;                                                     \
    _Pragma("unroll") for (int j = 0; j < 4; j++) {                            \
        int idx = tid + j * 256;                                               \
        int row = idx >> 3, slot = idx & 7;                                    \
        uint32_t so = (uint32_t)(row * 128 + ((slot ^ (row & 7)) << 4));       \
        int tok = (int)(stok[row] & 0xffffu);                                  \
        cp16(sbase + (uint32_t)(BUF) * 32768u + so,                            \
             g_hbuf + (size_t)tok * HID + k0 + slot * 8);                      \
        cp16(sbase + 16384u + (uint32_t)(BUF) * 32768u + so,                   \
             wmT + (size_t)(n0 + row) * HID + k0 + slot * 8);                  \
    }                                                                          \
    CP_COMMIT();                                                               \
} while (0)

    float acc[16][4];
    #pragma unroll
    for (int i = 0; i < 16; i++) { acc[i][0]=0.f; acc[i][1]=0.f; acc[i][2]=0.f; acc[i][3]=0.f; }

    int tileA = lane >> 3;
    int rlA   = ((tileA & 1) << 3) + (lane & 7);
    int thiA  = tileA >> 1;
    int r7A   = lane & 7;
    uint32_t aRowByte = (uint32_t)((wm * 64 + rlA) * 128);
    int l16 = lane & 15;
    int tB  = l16 >> 3;
    int rlB = l16 & 7;
    uint32_t bRowByte = (uint32_t)((wn * 32 + rlB) * 128);

    const int NST = HID / 64;                      // 16 chunks
    EG_ISSUE(0, 0);
    EG_ISSUE(1, 1);
    int buf = 0;
    for (int s = 0; s < NST; s++) {
        if (s + 1 < NST) CP_WAIT1(); else CP_WAIT0();
        __syncthreads();
        if (s + 2 < NST) {
            int nb = buf + 2; if (nb >= 3) nb -= 3;
            EG_ISSUE(s + 2, nb);
        }
        uint32_t Ab = sbase + (uint32_t)buf * 32768u;
        uint32_t Bb = Ab + 16384u;
        #pragma unroll
        for (int ks = 0; ks < 4; ks++) {
            uint32_t b0[4], b1[4];
            #pragma unroll
            for (int nt = 0; nt < 4; nt++) {
                uint32_t addr = Bb + bRowByte + (uint32_t)(nt * 1024)
                              + (uint32_t)(((ks * 2 + tB) ^ rlB) << 4);
                LDMX2(b0[nt], b1[nt], addr);
            }
            #pragma unroll
            for (int mt = 0; mt < 4; mt++) {
                uint32_t a0, a1, a2, a3;
                uint32_t addr = Ab + aRowByte + (uint32_t)(mt * 2048)
                              + (uint32_t)(((ks * 2 + thiA) ^ r7A) << 4);
                LDMX4(a0, a1, a2, a3, addr);
                #pragma unroll
                for (int nt = 0; nt < 4; nt++)
                    MMA_F16(acc[mt * 4 + nt], a0, a1, a2, a3, b0[nt], b1[nt]);
            }
        }
        buf++; if (buf >= 3) buf -= 3;
    }

    // epilogue: out[slot][tok][n] = w * (acc + cvec)
    int rr = lane >> 2, cc = (lane & 3) * 2;
    #pragma unroll
    for (int mt = 0; mt < 4; mt++) {
        #pragma unroll
        for (int half = 0; half < 2; half++) {
            int ml = wm * 64 + mt * 16 + rr + half * 8;
            if (m0 + ml >= cnt) continue;
            unsigned int pk = stok[ml];
            int tok = (int)(pk & 0xffffu), slot = (int)(pk >> 16);
            float w = swt[ml];
            float* outp = g_partial + (size_t)slot * NTOK * HID + (size_t)tok * HID;
            #pragma unroll
            for (int nt = 0; nt < 4; nt++) {
                int n = n0 + wn * 32 + nt * 8 + cc;
                const float* d = acc[mt * 4 + nt];
                float cv0 = g_cvec[e * HID + n], cv1 = g_cvec[e * HID + n + 1];
                float2 o;
                o.x = w * (d[half * 2 + 0] + cv0);
                o.y = w * (d[half * 2 + 1] + cv1);
                *(float2*)(outp + n) = o;
            }
        }
    }
#undef EG_ISSUE
}

// ---------------- k_aprep: A = fp16(p0 + p1) ----------------
__global__ void k_aprep() {
    int m = blockIdx.x;
    const float4* p0 = (const float4*)(g_partial + (size_t)m * HID);
    const float4* p1 = (const float4*)(g_partial + (size_t)NTOK * HID + (size_t)m * HID);
    __half2* a2 = (__half2*)(g_abuf + (size_t)m * HID);
    int i = threadIdx.x;
    float4 v0 = p0[i], v1 = p1[i];
    a2[2 * i]     = __floats2half2_rn(v0.x + v1.x, v0.y + v1.y);
    a2[2 * i + 1] = __floats2half2_rn(v0.z + v1.z, v0.w + v1.w);
}

// ---------------- k_vgemm2: fp16 mma GEMM, 128x128 tile, 3-stage cp.async + ldmatrix ----------------
// grid (NTOK/128=16, VOC/128=250), block 256 (8 warps = 2m x 4n, warp tile 64x32)
__global__ void __launch_bounds__(256, 2) k_vgemm2(const float* __restrict__ vb,
                                                   float* __restrict__ out) {
    extern __shared__ float vsm[];
    int tid = threadIdx.x;
    int lane = tid & 31, wid = tid >> 5;
    int wm = wid >> 2, wn = wid & 3;
    int m0 = blockIdx.x * 128, n0 = blockIdx.y * 128;
    const __half* Ag = g_abuf + (size_t)m0 * HID;
    const __half* Bg = g_wt   + (size_t)n0 * HID;
    uint32_t sbase = smem_u32(vsm);

#define VG_ISSUE(STAGE, BUF) do {                                              \
    int k0 = (STAGE) * 64;                                                     \
    _Pragma("unroll") for (int j = 0; j < 4; j++) {                            \
        int idx = tid + j * 256;                                               \
        int row = idx >> 3, slot = idx & 7;                                    \
        uint32_t so = (uint32_t)(row * 128 + ((slot ^ (row & 7)) << 4));       \
        cp16(sbase + (uint32_t)(BUF) * 32768u + so,                            \
             Ag + (size_t)row * HID + k0 + slot * 8);                          \
        cp16(sbase + 16384u + (uint32_t)(BUF) * 32768u + so,                   \
             Bg + (size_t)row * HID + k0 + slot * 8);                          \
    }                                                                          \
    CP_COMMIT();                                                               \
} while (0)

    float acc[16][4];
    #pragma unroll
    for (int i = 0; i < 16; i++) { acc[i][0]=0.f; acc[i][1]=0.f; acc[i][2]=0.f; acc[i][3]=0.f; }

    int tileA = lane >> 3;
    int rlA   = ((tileA & 1) << 3) + (lane & 7);
    int thiA  = tileA >> 1;
    int r7A   = lane & 7;
    uint32_t aRowByte = (uint32_t)((wm * 64 + rlA) * 128);
    int l16 = lane & 15;
    int tB  = l16 >> 3;
    int rlB = l16 & 7;
    uint32_t bRowByte = (uint32_t)((wn * 32 + rlB) * 128);

    const int NST = HID / 64;                      // 16 chunks
    VG_ISSUE(0, 0);
    VG_ISSUE(1, 1);
    int buf = 0;                                   // buf = s % 3
    for (int s = 0; s < NST; s++) {
        if (s + 1 < NST) CP_WAIT1(); else CP_WAIT0();
        __syncthreads();                           // stage s ready + all warps done with s-1
        if (s + 2 < NST) {
            int nb = buf + 2; if (nb >= 3) nb -= 3;
            VG_ISSUE(s + 2, nb);                   // overwrites buffer of stage s-1 (safe)
        }
        uint32_t Ab = sbase + (uint32_t)buf * 32768u;
        uint32_t Bb = Ab + 16384u;
        #pragma unroll
        for (int ks = 0; ks < 4; ks++) {
            uint32_t b0[4], b1[4];
            #pragma unroll
            for (int nt = 0; nt < 4; nt++) {
                uint32_t addr = Bb + bRowByte + (uint32_t)(nt * 1024)
                              + (uint32_t)(((ks * 2 + tB) ^ rlB) << 4);
                LDMX2(b0[nt], b1[nt], addr);
            }
            #pragma unroll
            for (int mt = 0; mt < 4; mt++) {
                uint32_t a0, a1, a2, a3;
                uint32_t addr = Ab + aRowByte + (uint32_t)(mt * 2048)
                              + (uint32_t)(((ks * 2 + thiA) ^ r7A) << 4);
                LDMX4(a0, a1, a2, a3, addr);
                #pragma unroll
                for (int nt = 0; nt < 4; nt++)
                    MMA_F16(acc[mt * 4 + nt], a0, a1, a2, a3, b0[nt], b1[nt]);
            }
        }
        buf++; if (buf >= 3) buf -= 3;
    }

    // epilogue
    int rr = lane >> 2, cc = (lane & 3) * 2;
    #pragma unroll
    for (int mt = 0; mt < 4; mt++) {
        int m = m0 + wm * 64 + mt * 16 + rr;
        #pragma unroll
        for (int nt = 0; nt < 4; nt++) {
            int n = n0 + wn * 32 + nt * 8 + cc;
            const float* d = acc[mt * 4 + nt];
            float2 bb = *(const float2*)(vb + n);
            float2 o0 = make_float2(d[0] + bb.x, d[1] + bb.y);
            float2 o1 = make_float2(d[2] + bb.x, d[3] + bb.y);
            *(float2*)(out + (size_t)m * VOC + n) = o0;
            *(float2*)(out + (size_t)(m + 8) * VOC + n) = o1;
        }
    }
#undef VG_ISSUE
}

// ---------------- launch ----------------
extern "C" void kernel_launch(void* const* d_in, const int* in_sizes, int n_in,
                              void* d_out, int out_size) {
    const int*   x    = (const int*)  d_in[0];
    const float* emb  = (const float*)d_in[1];
    const float* gw   = (const float*)d_in[2];
    const float* gb   = (const float*)d_in[3];
    const float* ew   = (const float*)d_in[4];
    const float* eb   = (const float*)d_in[5];
    const float* ela  = (const float*)d_in[6];
    const float* elb  = (const float*)d_in[7];
    const float* cv   = (const float*)d_in[8];
    const float* cimp = (const float*)d_in[9];
    const float* cla  = (const float*)d_in[10];
    const float* clb  = (const float*)d_in[11];
    const float* vw   = (const float*)d_in[12];
    const float* vb   = (const float*)d_in[13];
    float* out = (float*)d_out;

    cudaFuncSetAttribute(k_egemm3, cudaFuncAttributeMaxDynamicSharedMemorySize, 98304);
    cudaFuncSetAttribute(k_vgemm2, cudaFuncAttributeMaxDynamicSharedMemorySize, 98304);

    k_zero<<<1, 32>>>();
    k_prep<<<PREP_BLOCKS, 256>>>(ew, ela, elb, cimp, x, emb, gw, gb, vw);
    k_sumsel<<<dim3(HID / 256, NEXP, 8), 256>>>(cv);
    k_cvec<<<NEXP, 256>>>(cla, clb, eb);
    k_egemm3<<<dim3(HID / 128, NTOK / 128, NEXP), 256, 98304>>>();
    k_aprep<<<NTOK, 256>>>();
    k_vgemm2<<<dim3(NTOK / 128, VOC / 128), 256, 98304>>>(vb, out);
}

// round 15
// speedup vs baseline: 6.6924x; 1.0445x over previous
#include <cuda_runtime.h>
#include <cuda_fp16.h>
#include <stdint.h>

// Problem constants
#define NTOK 2048      // B*S = 2*1024
#define HID  1024
#define NEXP 8
#define VOC  32000
#define KVC  2048
#define LSCALE 0.25f   // ALPHA / RANK

// ---------------- scratch (device globals; no allocations) ----------------
__device__ __half g_hbuf[NTOK * HID];             // fp16 embedded tokens   4 MB
__device__ __half g_wmod[NEXP * HID * HID];       // fp16 (W+la@lb*s)^T    16 MB [e][f][h]
__device__ float  g_cvec[NEXP * HID];             // cache_vec + expert_b
__device__ float  g_partial[2 * NTOK * HID];      // per-slot outputs      16 MB
__device__ __half g_abuf[NTOK * HID];             // fp16(p0+p1)            4 MB
__device__ __half g_wt[(size_t)VOC * HID];        // fp16(vocab_w^T)       64 MB [n][k]
__device__ int    g_count[NEXP];                  // zero-init at load; reset by k_aprep
__device__ unsigned int g_plist[NEXP * NTOK];     // token | slot<<16
__device__ float  g_pw[NEXP * NTOK];
__device__ unsigned char g_self[NEXP * KVC];
__device__ float  g_msum_part[NEXP * 16 * HID];

__device__ __forceinline__ uint32_t smem_u32(const void* p) {
    uint32_t a;
    asm("{ .reg .u64 t; cvta.to.shared.u64 t, %1; cvt.u32.u64 %0, t; }" : "=r"(a) : "l"(p));
    return a;
}
__device__ __forceinline__ void cp16(uint32_t dst, const void* src) {
    asm volatile("cp.async.cg.shared.global [%0], [%1], 16;" :: "r"(dst), "l"(src) : "memory");
}
#define CP_COMMIT() asm volatile("cp.async.commit_group;" ::: "memory")
#define CP_WAIT1()  asm volatile("cp.async.wait_group 1;" ::: "memory")
#define CP_WAIT0()  asm volatile("cp.async.wait_group 0;" ::: "memory")

#define LDMX4(a0,a1,a2,a3,addr) \
    asm volatile("ldmatrix.sync.aligned.m8n8.x4.shared.b16 {%0,%1,%2,%3}, [%4];" \
        : "=r"(a0), "=r"(a1), "=r"(a2), "=r"(a3) : "r"(addr))
#define LDMX2(b0,b1,addr) \
    asm volatile("ldmatrix.sync.aligned.m8n8.x2.shared.b16 {%0,%1}, [%2];" \
        : "=r"(b0), "=r"(b1) : "r"(addr))
#define MMA_F16(d, A0,A1,A2,A3, B0,B1) \
    asm volatile("mma.sync.aligned.m16n8k16.row.col.f32.f16.f16.f32 " \
        "{%0,%1,%2,%3}, {%4,%5,%6,%7}, {%8,%9}, {%0,%1,%2,%3};" \
        : "+f"((d)[0]), "+f"((d)[1]), "+f"((d)[2]), "+f"((d)[3]) \
        : "r"(A0), "r"(A1), "r"(A2), "r"(A3), "r"(B0), "r"(B1))

// ---------------- k_prep: fused select | wmodT | route | wt ----------------
// flattened grid: [0,8) select, [8,2056) wmodT, [2056,4104) route, [4104,12104) wt
#define PREP_SEL0   0
#define PREP_WMOD0  8
#define PREP_ROUTE0 (PREP_WMOD0 + 2048)
#define PREP_WT0    (PREP_ROUTE0 + NTOK)
#define PREP_BLOCKS (PREP_WT0 + 8000)

// Shared-memory union: personas never overlap within a block -> max, not sum.
union PrepSm {
    float ts[64][65];                                    // wmodT / wt  (16.6 KB)
    struct { unsigned int sv[KVC]; int redi[256]; } sel; // select      ( 9.2 KB)
    struct { float hs[HID]; float sred[8][8]; } rt;      // route       ( 4.3 KB)
};

__global__ void __launch_bounds__(256) k_prep(
    const float* __restrict__ ew, const float* __restrict__ la, const float* __restrict__ lb,
    const float* __restrict__ imp,
    const int* __restrict__ x, const float* __restrict__ emb,
    const float* __restrict__ gw, const float* __restrict__ gb,
    const float* __restrict__ vw)
{
    __shared__ PrepSm sm;

    int bid = blockIdx.x;
    int tid = threadIdx.x;

    if (bid < PREP_WMOD0) {
        // ===== k_select (block = expert) =====
        int e = bid;
        int n = KVC - 128 * e;
        int k = n / 2;
        unsigned int* sv = sm.sel.sv;
        int* redi = sm.sel.redi;
        for (int i = tid; i < n; i += 256) sv[i] = __float_as_uint(imp[e * KVC + i]);
        __syncthreads();
        unsigned int T = 0;
        for (int bit = 31; bit >= 0; --bit) {
            unsigned int cand = T | (1u << bit);
            int c = 0;
            for (int i = tid; i < n; i += 256) c += (sv[i] >= cand);
            redi[tid] = c; __syncthreads();
            for (int s = 128; s > 0; s >>= 1) { if (tid < s) redi[tid] += redi[tid + s]; __syncthreads(); }
            int cnt = redi[0];
            __syncthreads();
            if (cnt >= k) T = cand;
        }
        int c = 0;
        for (int i = tid; i < n; i += 256) c += (sv[i] > T);
        redi[tid] = c; __syncthreads();
        for (int s = 128; s > 0; s >>= 1) { if (tid < s) redi[tid] += redi[tid + s]; __syncthreads(); }
        int g = redi[0];
        __syncthreads();
        for (int i = tid; i < n; i += 256) g_self[e * KVC + i] = (sv[i] > T) ? 1 : 0;
        __syncthreads();
        if (tid == 0) {
            int extra = k - g;
            for (int i = 0; i < n && extra > 0; i++) {
                if (sv[i] == T) { g_self[e * KVC + i] = 1; extra--; }
            }
        }
    } else if (bid < PREP_ROUTE0) {
        // ===== k_wmodT: g_wmod[e][f][h] = fp16(ew[e][h][f] + s*la@lb) =====
        int b = bid - PREP_WMOD0;
        int e = b >> 8;                      // /256
        int n0 = (b & 15) * 64;              // f tile
        int k0 = ((b >> 4) & 15) * 64;       // h tile
        const float* lbe = lb + (size_t)e * 4 * HID;
        #pragma unroll
        for (int r = 0; r < 16; r++) {
            int idx = tid + r * 256;
            int kk = idx / 64, nn = idx % 64;
            int h = k0 + kk, f = n0 + nn;
            const float* lar = la + ((size_t)e * HID + h) * 4;
            float v = ew[((size_t)e * HID + h) * HID + f]
                    + LSCALE * (lar[0] * lbe[f] + lar[1] * lbe[HID + f]
                               + lar[2] * lbe[2 * HID + f] + lar[3] * lbe[3 * HID + f]);
            sm.ts[kk][nn] = v;
        }
        __syncthreads();
        #pragma unroll
        for (int r = 0; r < 8; r++) {
            int idx = tid + r * 256;
            int nn = idx >> 5, kp = idx & 31;
            __half2 hp = __floats2half2_rn(sm.ts[kp * 2][nn], sm.ts[kp * 2 + 1][nn]);
            *(__half2*)(g_wmod + ((size_t)e * HID + n0 + nn) * HID + k0 + kp * 2) = hp;
        }
    } else if (bid < PREP_WT0) {
        // ===== k_route (block = token) =====
        int t = bid - PREP_ROUTE0;
        const float* er = emb + (size_t)x[t] * HID;
        float* hs = sm.rt.hs;
        float4* hs4 = (float4*)hs;
        __half2* hb2 = (__half2*)(g_hbuf + (size_t)t * HID);
        for (int i = tid; i < HID / 4; i += 256) {
            float4 v = ((const float4*)er)[i];
            hs4[i] = v;
            hb2[2 * i]     = __floats2half2_rn(v.x, v.y);
            hb2[2 * i + 1] = __floats2half2_rn(v.z, v.w);
        }
        __syncthreads();
        float p[8] = {0.f, 0.f, 0.f, 0.f, 0.f, 0.f, 0.f, 0.f};
        for (int i = tid; i < HID; i += 256) {
            float hv = hs[i];
            const float* g = gw + (size_t)i * 8;
            #pragma unroll
            for (int e2 = 0; e2 < 8; e2++) p[e2] += hv * g[e2];
        }
        #pragma unroll
        for (int off = 16; off > 0; off >>= 1)
            #pragma unroll
            for (int e2 = 0; e2 < 8; e2++) p[e2] += __shfl_down_sync(0xffffffffu, p[e2], off);
        int warp = tid / 32, lane = tid % 32;
        if (lane == 0)
            #pragma unroll
            for (int e2 = 0; e2 < 8; e2++) sm.rt.sred[e2][warp] = p[e2];
        __syncthreads();
        if (tid == 0) {
            float lg[8];
            #pragma unroll
            for (int e2 = 0; e2 < 8; e2++) {
                float s = 0.f;
                #pragma unroll
                for (int w = 0; w < 8; w++) s += sm.rt.sred[e2][w];
                lg[e2] = s + gb[e2];
            }
            int i1 = 0;
            #pragma unroll
            for (int e2 = 1; e2 < 8; e2++) if (lg[e2] > lg[i1]) i1 = e2;
            int i2 = -1;
            #pragma unroll
            for (int e2 = 0; e2 < 8; e2++) {
                if (e2 == i1) continue;
                if (i2 < 0 || lg[e2] > lg[i2]) i2 = e2;
            }
            float w1 = 1.f / (1.f + expf(lg[i2] - lg[i1]));
            float w2 = 1.f - w1;
            int p1 = atomicAdd(&g_count[i1], 1);
            g_plist[i1 * NTOK + p1] = (unsigned)t;
            g_pw[i1 * NTOK + p1] = w1;
            int p2 = atomicAdd(&g_count[i2], 1);
            g_plist[i2 * NTOK + p2] = (unsigned)t | (1u << 16);
            g_pw[i2 * NTOK + p2] = w2;
        }
    } else {
        // ===== k_wt: g_wt[n][k] = fp16(vocab_w[k][n]) =====
        int b = bid - PREP_WT0;              // 8000 blocks: 500 n-tiles x 16 k-tiles
        int n0 = (b % 500) * 64, k0 = (b / 500) * 64;
        #pragma unroll
        for (int r = 0; r < 16; r++) {
            int idx = tid + r * 256;
            int kk = idx / 64, nn = idx % 64;
            sm.ts[kk][nn] = vw[(size_t)(k0 + kk) * VOC + n0 + nn];
        }
        __syncthreads();
        #pragma unroll
        for (int r = 0; r < 8; r++) {
            int idx = tid + r * 256;
            int nn = idx >> 5, kp = idx & 31;
            __half2 hp = __floats2half2_rn(sm.ts[kp * 2][nn], sm.ts[kp * 2 + 1][nn]);
            *(__half2*)(g_wt + (size_t)(n0 + nn) * HID + k0 + kp * 2) = hp;
        }
    }
}

// ---------------- k2b: masked column partial sums (branchless, 16-way z-split) ----------------
// grid (HID/256, NEXP, 16), block 256
__global__ void k_sumsel(const float* __restrict__ cv) {
    int e = blockIdx.y, z = blockIdx.z;
    int col = blockIdx.x * 256 + threadIdx.x;
    int n = KVC - 128 * e;
    int r0 = z * 128;
    float* outp = g_msum_part + (size_t)(e * 16 + z) * HID + col;
    if (r0 >= n) { *outp = 0.f; return; }
    int cntr = min(128, n - r0);
    __shared__ float fm[128];
    if (threadIdx.x < 128)
        fm[threadIdx.x] = (threadIdx.x < cntr) ? (float)g_self[e * KVC + r0 + threadIdx.x] : 0.f;
    __syncthreads();
    float acc = 0.f;
    const float* base = cv + (size_t)e * KVC * HID + (size_t)r0 * HID + col;
    #pragma unroll 8
    for (int i = 0; i < 128; i++) {
        if (i < cntr) acc = fmaf(fm[i], base[(size_t)i * HID], acc);
    }
    *outp = acc;
}

// ---------------- k2c: cache vec = m + (m@la)@lb*s + expert_b ----------------
__global__ void k_cvec(const float* __restrict__ la, const float* __restrict__ lb,
                       const float* __restrict__ eb) {
    int e = blockIdx.x, tid = threadIdx.x;
    __shared__ float m[HID];
    __shared__ float red[4 * 256];
    int k = (KVC - 128 * e) / 2;
    float invk = 1.f / (float)k;
    for (int f = tid; f < HID; f += 256) {
        float s = 0.f;
        #pragma unroll
        for (int z = 0; z < 16; z++) s += g_msum_part[(size_t)(e * 16 + z) * HID + f];
        m[f] = s * invk;
    }
    __syncthreads();
    float u[4] = {0.f, 0.f, 0.f, 0.f};
    for (int f = tid; f < HID; f += 256) {
        float mv = m[f];
        const float* lr = la + ((size_t)e * HID + f) * 4;
        u[0] += mv * lr[0]; u[1] += mv * lr[1]; u[2] += mv * lr[2]; u[3] += mv * lr[3];
    }
    #pragma unroll
    for (int r = 0; r < 4; r++) red[r * 256 + tid] = u[r];
    __syncthreads();
    for (int s = 128; s > 0; s >>= 1) {
        if (tid < s)
            #pragma unroll
            for (int r = 0; r < 4; r++) red[r * 256 + tid] += red[r * 256 + tid + s];
        __syncthreads();
    }
    float u0 = red[0], u1 = red[256], u2 = red[512], u3 = red[768];
    const float* lbe = lb + (size_t)e * 4 * HID;
    for (int f = tid; f < HID; f += 256) {
        g_cvec[e * HID + f] = m[f]
            + LSCALE * (u0 * lbe[f] + u1 * lbe[HID + f] + u2 * lbe[2 * HID + f] + u3 * lbe[3 * HID + f])
            + eb[e * HID + f];
    }
}

// ---------------- k_egemm3: per-expert gathered fp16 mma GEMM, 128x128 tile ----------------
// grid (HID/128=8, NTOK/128=16, NEXP), block 256 (8 warps = 2m x 4n, warp tile 64x32)
__global__ void __launch_bounds__(256, 2) k_egemm3() {
    extern __shared__ float esm[];
    __shared__ unsigned int stok[128];
    __shared__ float swt[128];

    int e = blockIdx.z;
    int cnt = g_count[e];
    int m0 = blockIdx.y * 128;
    if (m0 >= cnt) return;
    int n0 = blockIdx.x * 128;

    int tid = threadIdx.x;
    int lane = tid & 31, wid = tid >> 5;
    int wm = wid >> 2, wn = wid & 3;
    uint32_t sbase = smem_u32(esm);

    if (tid < 128) {
        int p = m0 + tid;
        if (p < cnt) { stok[tid] = g_plist[e * NTOK + p]; swt[tid] = g_pw[e * NTOK + p]; }
        else         { stok[tid] = 0u;                    swt[tid] = 0.f; }
    }
    __syncthreads();

    const __half* wmT = g_wmod + (size_t)e * HID * HID;

#define EG_ISSUE(STAGE, BUF) do {                                              \
    int k0 = (STAGE) * 64;                                                     \
    _Pragma("unroll") for (int j = 0; j < 4; j++) {                            \
        int idx = tid + j * 256;                                               \
        int row = idx >> 3, slot = idx & 7;                                    \
        uint32_t so = (uint32_t)(row * 128 + ((slot ^ (row & 7)) << 4));       \
        int tok = (int)(stok[row] & 0xffffu);                                  \
        cp16(sbase + (uint32_t)(BUF) * 32768u + so,                            \
             g_hbuf + (size_t)tok * HID + k0 + slot * 8);                      \
        cp16(sbase + 16384u + (uint32_t)(BUF) * 32768u + so,                   \
             wmT + (size_t)(n0 + row) * HID + k0 + slot * 8);                  \
    }                                                                          \
    CP_COMMIT();                                                               \
} while (0)

    float acc[16][4];
    #pragma unroll
    for (int i = 0; i < 16; i++) { acc[i][0]=0.f; acc[i][1]=0.f; acc[i][2]=0.f; acc[i][3]=0.f; }

    int tileA = lane >> 3;
    int rlA   = ((tileA & 1) << 3) + (lane & 7);
    int thiA  = tileA >> 1;
    int r7A   = lane & 7;
    uint32_t aRowByte = (uint32_t)((wm * 64 + rlA) * 128);
    int l16 = lane & 15;
    int tB  = l16 >> 3;
    int rlB = l16 & 7;
    uint32_t bRowByte = (uint32_t)((wn * 32 + rlB) * 128);

    const int NST = HID / 64;                      // 16 chunks
    EG_ISSUE(0, 0);
    EG_ISSUE(1, 1);
    int buf = 0;
    for (int s = 0; s < NST; s++) {
        if (s + 1 < NST) CP_WAIT1(); else CP_WAIT0();
        __syncthreads();
        if (s + 2 < NST) {
            int nb = buf + 2; if (nb >= 3) nb -= 3;
            EG_ISSUE(s + 2, nb);
        }
        uint32_t Ab = sbase + (uint32_t)buf * 32768u;
        uint32_t Bb = Ab + 16384u;
        #pragma unroll
        for (int ks = 0; ks < 4; ks++) {
            uint32_t b0[4], b1[4];
            #pragma unroll
            for (int nt = 0; nt < 4; nt++) {
                uint32_t addr = Bb + bRowByte + (uint32_t)(nt * 1024)
                              + (uint32_t)(((ks * 2 + tB) ^ rlB) << 4);
                LDMX2(b0[nt], b1[nt], addr);
            }
            #pragma unroll
            for (int mt = 0; mt < 4; mt++) {
                uint32_t a0, a1, a2, a3;
                uint32_t addr = Ab + aRowByte + (uint32_t)(mt * 2048)
                              + (uint32_t)(((ks * 2 + thiA) ^ r7A) << 4);
                LDMX4(a0, a1, a2, a3, addr);
                #pragma unroll
                for (int nt = 0; nt < 4; nt++)
                    MMA_F16(acc[mt * 4 + nt], a0, a1, a2, a3, b0[nt], b1[nt]);
            }
        }
        buf++; if (buf >= 3) buf -= 3;
    }

    // epilogue: out[slot][tok][n] = w * (acc + cvec)
    int rr = lane >> 2, cc = (lane & 3) * 2;
    #pragma unroll
    for (int mt = 0; mt < 4; mt++) {
        #pragma unroll
        for (int half = 0; half < 2; half++) {
            int ml = wm * 64 + mt * 16 + rr + half * 8;
            if (m0 + ml >= cnt) continue;
            unsigned int pk = stok[ml];
            int tok = (int)(pk & 0xffffu), slot = (int)(pk >> 16);
            float w = swt[ml];
            float* outp = g_partial + (size_t)slot * NTOK * HID + (size_t)tok * HID;
            #pragma unroll
            for (int nt = 0; nt < 4; nt++) {
                int n = n0 + wn * 32 + nt * 8 + cc;
                const float* d = acc[mt * 4 + nt];
                float cv0 = g_cvec[e * HID + n], cv1 = g_cvec[e * HID + n + 1];
                float2 o;
                o.x = w * (d[half * 2 + 0] + cv0);
                o.y = w * (d[half * 2 + 1] + cv1);
                *(float2*)(outp + n) = o;
            }
        }
    }
#undef EG_ISSUE
}

// ---------------- k_aprep: A = fp16(p0 + p1); also resets g_count for next call ----------------
__global__ void k_aprep() {
    int m = blockIdx.x;
    if (m == 0 && threadIdx.x < NEXP) g_count[threadIdx.x] = 0;
    const float4* p0 = (const float4*)(g_partial + (size_t)m * HID);
    const float4* p1 = (const float4*)(g_partial + (size_t)NTOK * HID + (size_t)m * HID);
    __half2* a2 = (__half2*)(g_abuf + (size_t)m * HID);
    int i = threadIdx.x;
    float4 v0 = p0[i], v1 = p1[i];
    a2[2 * i]     = __floats2half2_rn(v0.x + v1.x, v0.y + v1.y);
    a2[2 * i + 1] = __floats2half2_rn(v0.z + v1.z, v0.w + v1.w);
}

// ---------------- k_vgemm2: fp16 mma GEMM, 128x128 tile, 3-stage cp.async + ldmatrix ----------------
// grid (NTOK/128=16, VOC/128=250), block 256 (8 warps = 2m x 4n, warp tile 64x32)
__global__ void __launch_bounds__(256, 2) k_vgemm2(const float* __restrict__ vb,
                                                   float* __restrict__ out) {
    extern __shared__ float vsm[];
    int tid = threadIdx.x;
    int lane = tid & 31, wid = tid >> 5;
    int wm = wid >> 2, wn = wid & 3;
    int m0 = blockIdx.x * 128, n0 = blockIdx.y * 128;
    const __half* Ag = g_abuf + (size_t)m0 * HID;
    const __half* Bg = g_wt   + (size_t)n0 * HID;
    uint32_t sbase = smem_u32(vsm);

#define VG_ISSUE(STAGE, BUF) do {                                              \
    int k0 = (STAGE) * 64;                                                     \
    _Pragma("unroll") for (int j = 0; j < 4; j++) {                            \
        int idx = tid + j * 256;                                               \
        int row = idx >> 3, slot = idx & 7;                                    \
        uint32_t so = (uint32_t)(row * 128 + ((slot ^ (row & 7)) << 4));       \
        cp16(sbase + (uint32_t)(BUF) * 32768u + so,                            \
             Ag + (size_t)row * HID + k0 + slot * 8);                          \
        cp16(sbase + 16384u + (uint32_t)(BUF) * 32768u + so,                   \
             Bg + (size_t)row * HID + k0 + slot * 8);                          \
    }                                                                          \
    CP_COMMIT();                                                               \
} while (0)

    float acc[16][4];
    #pragma unroll
    for (int i = 0; i < 16; i++) { acc[i][0]=0.f; acc[i][1]=0.f; acc[i][2]=0.f; acc[i][3]=0.f; }

    int tileA = lane >> 3;
    int rlA   = ((tileA & 1) << 3) + (lane & 7);
    int thiA  = tileA >> 1;
    int r7A   = lane & 7;
    uint32_t aRowByte = (uint32_t)((wm * 64 + rlA) * 128);
    int l16 = lane & 15;
    int tB  = l16 >> 3;
    int rlB = l16 & 7;
    uint32_t bRowByte = (uint32_t)((wn * 32 + rlB) * 128);

    const int NST = HID / 64;                      // 16 chunks
    VG_ISSUE(0, 0);
    VG_ISSUE(1, 1);
    int buf = 0;                                   // buf = s % 3
    for (int s = 0; s < NST; s++) {
        if (s + 1 < NST) CP_WAIT1(); else CP_WAIT0();
        __syncthreads();                           // stage s ready + all warps done with s-1
        if (s + 2 < NST) {
            int nb = buf + 2; if (nb >= 3) nb -= 3;
            VG_ISSUE(s + 2, nb);                   // overwrites buffer of stage s-1 (safe)
        }
        uint32_t Ab = sbase + (uint32_t)buf * 32768u;
        uint32_t Bb = Ab + 16384u;
        #pragma unroll
        for (int ks = 0; ks < 4; ks++) {
            uint32_t b0[4], b1[4];
            #pragma unroll
            for (int nt = 0; nt < 4; nt++) {
                uint32_t addr = Bb + bRowByte + (uint32_t)(nt * 1024)
                              + (uint32_t)(((ks * 2 + tB) ^ rlB) << 4);
                LDMX2(b0[nt], b1[nt], addr);
            }
            #pragma unroll
            for (int mt = 0; mt < 4; mt++) {
                uint32_t a0, a1, a2, a3;
                uint32_t addr = Ab + aRowByte + (uint32_t)(mt * 2048)
                              + (uint32_t)(((ks * 2 + thiA) ^ r7A) << 4);
                LDMX4(a0, a1, a2, a3, addr);
                #pragma unroll
                for (int nt = 0; nt < 4; nt++)
                    MMA_F16(acc[mt * 4 + nt], a0, a1, a2, a3, b0[nt], b1[nt]);
            }
        }
        buf++; if (buf >= 3) buf -= 3;
    }

    // epilogue
    int rr = lane >> 2, cc = (lane & 3) * 2;
    #pragma unroll
    for (int mt = 0; mt < 4; mt++) {
        int m = m0 + wm * 64 + mt * 16 + rr;
        #pragma unroll
        for (int nt = 0; nt < 4; nt++) {
            int n = n0 + wn * 32 + nt * 8 + cc;
            const float* d = acc[mt * 4 + nt];
            float2 bb = *(const float2*)(vb + n);
            float2 o0 = make_float2(d[0] + bb.x, d[1] + bb.y);
            float2 o1 = make_float2(d[2] + bb.x, d[3] + bb.y);
            *(float2*)(out + (size_t)m * VOC + n) = o0;
            *(float2*)(out + (size_t)(m + 8) * VOC + n) = o1;
        }
    }
#undef VG_ISSUE
}

// ---------------- launch ----------------
extern "C" void kernel_launch(void* const* d_in, const int* in_sizes, int n_in,
                              void* d_out, int out_size) {
    const int*   x    = (const int*)  d_in[0];
    const float* emb  = (const float*)d_in[1];
    const float* gw   = (const float*)d_in[2];
    const float* gb   = (const float*)d_in[3];
    const float* ew   = (const float*)d_in[4];
    const float* eb   = (const float*)d_in[5];
    const float* ela  = (const float*)d_in[6];
    const float* elb  = (const float*)d_in[7];
    const float* cv   = (const float*)d_in[8];
    const float* cimp = (const float*)d_in[9];
    const float* cla  = (const float*)d_in[10];
    const float* clb  = (const float*)d_in[11];
    const float* vw   = (const float*)d_in[12];
    const float* vb   = (const float*)d_in[13];
    float* out = (float*)d_out;

    cudaFuncSetAttribute(k_egemm3, cudaFuncAttributeMaxDynamicSharedMemorySize, 98304);
    cudaFuncSetAttribute(k_vgemm2, cudaFuncAttributeMaxDynamicSharedMemorySize, 98304);

    k_prep<<<PREP_BLOCKS, 256>>>(ew, ela, elb, cimp, x, emb, gw, gb, vw);
    k_sumsel<<<dim3(HID / 256, NEXP, 16), 256>>>(cv);
    k_cvec<<<NEXP, 256>>>(cla, clb, eb);
    k_egemm3<<<dim3(HID / 128, NTOK / 128, NEXP), 256, 98304>>>();
    k_aprep<<<NTOK, 256>>>();
    k_vgemm2<<<dim3(NTOK / 128, VOC / 128), 256, 98304>>>(vb, out);
}